// round 12
// baseline (speedup 1.0000x reference)
#include <cuda_runtime.h>
#include <cuda_bf16.h>
#include <math.h>
#include <stdint.h>

#define Bc 8
#define Nn 8192
#define Sc 2048
#define Kc 32
#define Dc 64
#define PP (Bc*Sc*Kc)   // 524288 positions
#define NG (PP/32)      // 16384 k-groups

// ---------------- scratch ---------------------------------------------------
__device__ float g_X0[8   * PP];
__device__ float g_Y1[32  * PP];
__device__ float g_Y2[64  * PP];
__device__ float g_Y3[128 * PP];
__device__ float g_mx[256 * NG];
__device__ float g_mn[256 * NG];
__device__ int   g_gidx[Sc*Kc];
__device__ double g_sum[4][256];
__device__ double g_sq [4][256];
__device__ float g_scale[4][256];
__device__ float g_shift[4][256];

__device__ __forceinline__ float clamp_ac(float x) {
    return fminf(fmaxf(x, -0.9999999f), 0.9999999f);
}

// =================== warp MMA + cp.async helpers (baseline PTX) ============
__device__ __forceinline__ uint32_t smem_u32(const void* p) {
    uint32_t a;
    asm("{ .reg .u64 t; cvta.to.shared.u64 t, %1; cvt.u32.u64 %0, t; }"
        : "=r"(a) : "l"(p));
    return a;
}
__device__ __forceinline__ void ldsm4(uint32_t* r, uint32_t a) {
    asm volatile("ldmatrix.sync.aligned.m8n8.x4.shared.b16 {%0,%1,%2,%3}, [%4];"
        : "=r"(r[0]), "=r"(r[1]), "=r"(r[2]), "=r"(r[3]) : "r"(a));
}
__device__ __forceinline__ void ldsm4t(uint32_t* r, uint32_t a) {
    asm volatile("ldmatrix.sync.aligned.m8n8.x4.trans.shared.b16 {%0,%1,%2,%3}, [%4];"
        : "=r"(r[0]), "=r"(r[1]), "=r"(r[2]), "=r"(r[3]) : "r"(a));
}
__device__ __forceinline__ void mma_bf16(float* d, const uint32_t* a, const uint32_t* b) {
    asm volatile("mma.sync.aligned.m16n8k16.row.col.f32.bf16.bf16.f32 "
        "{%0,%1,%2,%3}, {%4,%5,%6,%7}, {%8,%9}, {%0,%1,%2,%3};"
        : "+f"(d[0]), "+f"(d[1]), "+f"(d[2]), "+f"(d[3])
        : "r"(a[0]), "r"(a[1]), "r"(a[2]), "r"(a[3]), "r"(b[0]), "r"(b[1]));
}
__device__ __forceinline__ void cpa16(uint32_t d, const void* s) {
    asm volatile("cp.async.ca.shared.global [%0], [%1], 16;" :: "r"(d), "l"(s));
}
__device__ __forceinline__ void cpa4(uint32_t d, const void* s) {
    asm volatile("cp.async.ca.shared.global [%0], [%1], 4;" :: "r"(d), "l"(s));
}
#define CPA_COMMIT() asm volatile("cp.async.commit_group;" ::: "memory")
#define CPA_WAIT0()  asm volatile("cp.async.wait_group 0;" ::: "memory")

__device__ __forceinline__ uint32_t pack_hi2(float a, float b, float& ra, float& rb) {
    __nv_bfloat16 ha = __float2bfloat16_rn(a), hb = __float2bfloat16_rn(b);
    ra = a - __bfloat162float(ha);
    rb = b - __bfloat162float(hb);
    return (uint32_t)__bfloat16_as_ushort(ha) | ((uint32_t)__bfloat16_as_ushort(hb) << 16);
}
__device__ __forceinline__ uint32_t pack2(float a, float b) {
    return (uint32_t)__bfloat16_as_ushort(__float2bfloat16_rn(a))
         | ((uint32_t)__bfloat16_as_ushort(__float2bfloat16_rn(b)) << 16);
}

// ---------------------------------------------------------------------------
// k_rif: unchanged (passing since R5).
// ---------------------------------------------------------------------------
__global__ void __launch_bounds__(256) k_rif(const float* __restrict__ contour,
                                             const float* __restrict__ loa,
                                             float* __restrict__ out)
{
    const unsigned FULL = 0xffffffffu;
    int tid  = threadIdx.x;
    if (blockIdx.x == 0) {
        #pragma unroll
        for (int j = 0; j < 4; ++j) {
            ((double*)g_sum)[tid + j*256] = 0.0;
            ((double*)g_sq )[tid + j*256] = 0.0;
        }
    }
    int w    = blockIdx.x * 8 + (tid >> 5);
    int lane = tid & 31;
    int b = w >> 11;
    int s = w & (Sc - 1);

    int i0;
    if (s == Sc - 1) i0 = Nn - 1;
    else {
        float t = __fdiv_rn((float)s, 2047.0f);
        float v = __fmul_rn(8191.0f, t);
        i0 = (int)v;
    }
    int n = (i0 - (Kc/2) + lane) & (Nn - 1);
    if (b == 0) g_gidx[s*Kc + lane] = n;

    const float* cp = contour + ((size_t)b*Nn + i0)*3;
    float spx = cp[0], spy = cp[1], spz = cp[2];
    const float* ap = loa + ((size_t)b*Nn + i0)*3;
    float ax = ap[0], ay = ap[1], az = ap[2];

    if (lane < 3) {
        out[(b*Sc + s)*3 + lane]           = cp[lane];
        out[Bc*Sc*3 + (b*Sc + s)*3 + lane] = ap[lane];
    }

    const float* pp_ = contour + ((size_t)b*Nn + n)*3;
    float lx = pp_[0] - spx, ly = pp_[1] - spy, lz = pp_[2] - spz;
    const float* lp = loa + ((size_t)b*Nn + n)*3;
    float nlx = lp[0], nly = lp[1], nlz = lp[2];

    float sq = lx*lx + ly*ly + lz*lz;
    float d1 = (sq > 0.f) ? sqrtf(sq) : 0.f;
    float inv = (d1 > 0.f) ? (1.f / d1) : 0.f;
    float ux = lx*inv, uy = ly*inv, uz = lz*inv;

    int pl = (lane + 31) & 31;
    float plx = __shfl_sync(FULL, lx, pl);
    float ply = __shfl_sync(FULL, ly, pl);
    float plz = __shfl_sync(FULL, lz, pl);
    float pnlx = __shfl_sync(FULL, nlx, pl);
    float pnly = __shfl_sync(FULL, nly, pl);
    float pnlz = __shfl_sync(FULL, nlz, pl);
    float pux = __shfl_sync(FULL, ux, pl);
    float puy = __shfl_sync(FULL, uy, pl);
    float puz = __shfl_sync(FULL, uz, pl);

    float ivx = lx - plx, ivy = ly - ply, ivz = lz - plz;
    float isq = ivx*ivx + ivy*ivy + ivz*ivz;
    float idn = (isq > 0.f) ? sqrtf(isq) : 0.f;
    float ii  = (idn > 0.f) ? (1.f / idn) : 0.f;
    float iux = ivx*ii, iuy = ivy*ii, iuz = ivz*ii;

    float a1 = ux*ax + uy*ay + uz*az;
    float a2 = ux*nlx + uy*nly + uz*nlz;
    float a3 = acosf(clamp_ac(nlx*ax + nly*ay + nlz*az));
    float a4 = iux*nlx + iuy*nly + iuz*nlz;
    float a5 = iux*pnlx + iuy*pnly + iuz*pnlz;
    float a6 = acosf(clamp_ac(nlx*pnlx + nly*pnly + nlz*pnlz));
    float d2 = acosf(clamp_ac(ux*pux + uy*puy + uz*puz));

    size_t p = (size_t)(b*Sc + s)*Kc + lane;
    g_X0[0*(size_t)PP + p] = d1;
    g_X0[1*(size_t)PP + p] = d2;
    g_X0[2*(size_t)PP + p] = a1;
    g_X0[3*(size_t)PP + p] = a2;
    g_X0[4*(size_t)PP + p] = a3;
    g_X0[5*(size_t)PP + p] = a4;
    g_X0[6*(size_t)PP + p] = a5;
    g_X0[7*(size_t)PP + p] = a6;
}

// ---------------------------------------------------------------------------
// FFMA conv for small layers 0 (8->32) and 1 (32->64). Unchanged (passing).
// ---------------------------------------------------------------------------
template<int CIN, int COUT, int TILE_O, int MODE, int LAYER>
__global__ void __launch_bounds__(256) k_conv(const float* __restrict__ W,
                                              const float* __restrict__ bias)
{
    constexpr int OW = TILE_O / 16;
    constexpr int PL = (LAYER > 0) ? (LAYER - 1) : 0;

    const float* Xin  = (LAYER == 0) ? g_X0 : g_Y1;
    float*       Yout = (LAYER == 0) ? g_Y1 : g_Y2;

    __shared__ __align__(16) float sW[8][TILE_O];
    __shared__ __align__(16) float sX[8][128];
    __shared__ float sSc[CIN];
    __shared__ float sSh[CIN];

    int tid = threadIdx.x;
    int o0  = blockIdx.y * TILE_O;
    int p0  = blockIdx.x * 128;

    if (MODE >= 1) {
        if (tid < CIN) { sSc[tid] = g_scale[PL][tid]; sSh[tid] = g_shift[PL][tid]; }
    }
    __syncthreads();

    int tx = tid & 15, ty = tid >> 4;
    int kcl = tid >> 5;
    int pp4 = (tid & 31) * 4;

    float acc[OW][8];
    #pragma unroll
    for (int i = 0; i < OW; ++i)
        #pragma unroll
        for (int j = 0; j < 8; ++j) acc[i][j] = 0.f;

    #pragma unroll 1
    for (int cc = 0; cc < CIN/8; ++cc) {
        int c0 = cc * 8;
        for (int idx = tid; idx < TILE_O*8; idx += 256) {
            int o = idx & (TILE_O - 1), c = idx / TILE_O;
            sW[c][o] = W[(o0 + o)*CIN + c0 + c];
        }
        {
            int c = c0 + kcl;
            float4 v;
            if (MODE == 0) {
                v = *(const float4*)&Xin[(size_t)c*PP + p0 + pp4];
            } else {
                float4 r = *(const float4*)&Xin[(size_t)c*PP + p0 + pp4];
                float scv = sSc[c], shv = sSh[c];
                v.x = fmaxf(fmaf(r.x, scv, shv), 0.f);
                v.y = fmaxf(fmaf(r.y, scv, shv), 0.f);
                v.z = fmaxf(fmaf(r.z, scv, shv), 0.f);
                v.w = fmaxf(fmaf(r.w, scv, shv), 0.f);
            }
            *(float4*)&sX[kcl][pp4] = v;
        }
        __syncthreads();

        #pragma unroll
        for (int kc = 0; kc < 8; ++kc) {
            float4 xa = ((const float4*)sX[kc])[tx*2];
            float4 xb = ((const float4*)sX[kc])[tx*2 + 1];
            float xr[8] = {xa.x, xa.y, xa.z, xa.w, xb.x, xb.y, xb.z, xb.w};
            float wr[OW];
            if constexpr (OW == 4) {
                float4 wa = ((const float4*)sW[kc])[ty];
                wr[0]=wa.x; wr[1]=wa.y; wr[2]=wa.z; wr[3]=wa.w;
            } else {
                #pragma unroll
                for (int i = 0; i < OW; ++i) wr[i] = sW[kc][ty*OW + i];
            }
            #pragma unroll
            for (int i = 0; i < OW; ++i)
                #pragma unroll
                for (int j = 0; j < 8; ++j)
                    acc[i][j] = fmaf(wr[i], xr[j], acc[i][j]);
        }
        __syncthreads();
    }

    #pragma unroll
    for (int i = 0; i < OW; ++i) {
        int o = o0 + ty*OW + i;
        float bo = bias[o];
        float y[8];
        #pragma unroll
        for (int j = 0; j < 8; ++j) y[j] = acc[i][j] + bo;

        *(float4*)&Yout[(size_t)o*PP + p0 + tx*8]     = make_float4(y[0], y[1], y[2], y[3]);
        *(float4*)&Yout[(size_t)o*PP + p0 + tx*8 + 4] = make_float4(y[4], y[5], y[6], y[7]);

        float s1 = 0.f, s2 = 0.f;
        #pragma unroll
        for (int j = 0; j < 8; ++j) { s1 += y[j]; s2 += y[j]*y[j]; }
        #pragma unroll
        for (int off = 1; off <= 8; off <<= 1) {
            s1 += __shfl_xor_sync(0xffffffffu, s1, off);
            s2 += __shfl_xor_sync(0xffffffffu, s2, off);
        }
        if (tx == 0) {
            atomicAdd(&g_sum[LAYER][o], (double)s1);
            atomicAdd(&g_sq [LAYER][o], (double)s2);
        }
    }
}

// ===========================================================================
// h_fl1: pipelined warp-MMA bf16-split GEMM, layer 2 (128->128), N-tile 128.
// smem: Xh@0 Xl@32K Wh@64K Wl@96K | stage@128K (128 rows x 528B) | misc.
// Pipeline: pack(stage->X) -> sync -> cp.async(next->stage) -> MMA -> wait+sync.
// ===========================================================================
#define FL1_STRIDE 528
#define FL1_STAGE  131072
#define FL1_MISC   (131072 + 128*FL1_STRIDE)
#define FL1_SMEM   (FL1_MISC + 1024)
__global__ void __launch_bounds__(512) h_fl1(const float* __restrict__ W,
                                             const float* __restrict__ bias,
                                             const float* __restrict__ fmaps)
{
    extern __shared__ char smem[];
    const uint32_t XH = 0, XL = 32768, WH = 65536, WL = 98304;
    float* sSc = (float*)(smem + FL1_MISC);
    float* sSh = (float*)(smem + FL1_MISC + 256);
    uint32_t sb = smem_u32(smem);

    int tid = threadIdx.x, lane = tid & 31, wid = tid >> 5;
    int wm = wid & 3, wn = wid >> 2;

    if (tid < 64) { sSc[tid] = g_scale[1][tid]; sSh[tid] = g_shift[1][tid]; }

    // W -> smem bf16 hi/lo, swizzled rows of 256B
    {
        int o = tid >> 2, c0 = (tid & 3) * 32;
        const float* wr = W + o*128 + c0;
        uint32_t rowb = (uint32_t)o * 256;
        #pragma unroll
        for (int j = 0; j < 16; ++j) {
            int c = c0 + 2*j;
            float ra, rb;
            uint32_t hi = pack_hi2(wr[2*j], wr[2*j+1], ra, rb);
            uint32_t lo = pack2(ra, rb);
            uint32_t byt = rowb + ((((c >> 3) ^ (o & 7)) & 15) << 4) + (c & 7)*2;
            *(uint32_t*)(smem + WH + byt) = hi;
            *(uint32_t*)(smem + WL + byt) = lo;
        }
    }

    int fc  = tid >> 2;              // 0..127 channel
    int fn0 = (tid & 3) * 32;        // 0/32/64/96 position offset
    uint32_t sdst = sb + FL1_STAGE + (uint32_t)fc*FL1_STRIDE + (uint32_t)fn0*4;

    int r0 = wm*32 + (lane >> 2);
    float bs[4] = { bias[r0], bias[r0 + 8], bias[r0 + 16], bias[r0 + 24] };
    double d1a[4] = {0,0,0,0}, d2a[4] = {0,0,0,0};

    // ---- prologue: stage first tile ----
    int tile0 = blockIdx.x;
    if (tile0 < PP/128) {
        int p0 = tile0 * 128, bb = p0 >> 16;
        if (fc < 64) {
            const float* src = &g_Y2[(size_t)fc*PP + p0 + fn0];
            #pragma unroll
            for (int j = 0; j < 8; ++j) cpa16(sdst + j*16, src + j*4);
        } else {
            const float* fp = fmaps + ((size_t)bb*Dc + (fc - 64))*Nn;
            const int4* gi = (const int4*)&g_gidx[(p0 & 65535) + fn0];
            #pragma unroll
            for (int j = 0; j < 8; ++j) {
                int4 ix = gi[j];
                cpa4(sdst + j*16,      fp + ix.x);
                cpa4(sdst + j*16 + 4,  fp + ix.y);
                cpa4(sdst + j*16 + 8,  fp + ix.z);
                cpa4(sdst + j*16 + 12, fp + ix.w);
            }
        }
    }
    CPA_COMMIT(); CPA_WAIT0();
    __syncthreads();

    for (int tile = tile0; tile < PP/128; tile += gridDim.x) {
        int p0 = tile * 128;

        // ---- pack stage -> XH/XL (BN+relu for c<64; raw copy for c>=64) ----
        {
            const float* sv = (const float*)(smem + FL1_STAGE + (size_t)fc*FL1_STRIDE) + fn0;
            float v[32];
            if (fc < 64) {
                float scv = sSc[fc], shv = sSh[fc];
                #pragma unroll
                for (int j = 0; j < 8; ++j) {
                    float4 r = ((const float4*)sv)[j];
                    v[4*j+0] = fmaxf(fmaf(r.x, scv, shv), 0.f);
                    v[4*j+1] = fmaxf(fmaf(r.y, scv, shv), 0.f);
                    v[4*j+2] = fmaxf(fmaf(r.z, scv, shv), 0.f);
                    v[4*j+3] = fmaxf(fmaf(r.w, scv, shv), 0.f);
                }
            } else {
                #pragma unroll
                for (int j = 0; j < 8; ++j) {
                    float4 r = ((const float4*)sv)[j];
                    v[4*j+0] = r.x; v[4*j+1] = r.y; v[4*j+2] = r.z; v[4*j+3] = r.w;
                }
            }
            uint32_t rowb = (uint32_t)fc * 256;
            #pragma unroll
            for (int j = 0; j < 16; ++j) {
                int n = fn0 + 2*j;
                float ra, rb;
                uint32_t hi = pack_hi2(v[2*j], v[2*j+1], ra, rb);
                uint32_t lo = pack2(ra, rb);
                uint32_t byt = rowb + ((((n >> 3) ^ (fc & 7)) & 15) << 4) + (n & 7)*2;
                *(uint32_t*)(smem + XH + byt) = hi;
                *(uint32_t*)(smem + XL + byt) = lo;
            }
        }
        __syncthreads();   // X ready; stage free for next prefetch

        // ---- prefetch next tile into stage (overlaps MMA below) ----
        int nxt = tile + gridDim.x;
        if (nxt < PP/128) {
            int p0n = nxt * 128, bbn = p0n >> 16;
            if (fc < 64) {
                const float* src = &g_Y2[(size_t)fc*PP + p0n + fn0];
                #pragma unroll
                for (int j = 0; j < 8; ++j) cpa16(sdst + j*16, src + j*4);
            } else {
                const float* fp = fmaps + ((size_t)bbn*Dc + (fc - 64))*Nn;
                const int4* gi = (const int4*)&g_gidx[(p0n & 65535) + fn0];
                #pragma unroll
                for (int j = 0; j < 8; ++j) {
                    int4 ix = gi[j];
                    cpa4(sdst + j*16,      fp + ix.x);
                    cpa4(sdst + j*16 + 4,  fp + ix.y);
                    cpa4(sdst + j*16 + 8,  fp + ix.z);
                    cpa4(sdst + j*16 + 12, fp + ix.w);
                }
            }
        }
        CPA_COMMIT();

        // ---- MMA ----
        float acc[2][4][4];
        #pragma unroll
        for (int i = 0; i < 2; ++i)
            #pragma unroll
            for (int j = 0; j < 4; ++j)
                #pragma unroll
                for (int q = 0; q < 4; ++q) acc[i][j][q] = 0.f;

        #pragma unroll
        for (int s = 0; s < 8; ++s) {
            uint32_t Ah[8], Al[8], Bh[8], Bl[8];
            #pragma unroll
            for (int mf = 0; mf < 2; ++mf) {
                int rr = wm*32 + mf*16 + (lane & 15);
                uint32_t g = (uint32_t)(2*s + (lane >> 4));
                uint32_t byt = (uint32_t)rr*256 + (((g ^ (rr & 7)) & 15) << 4);
                ldsm4(Ah + mf*4, sb + WH + byt);
                ldsm4(Al + mf*4, sb + WL + byt);
            }
            #pragma unroll
            for (int half = 0; half < 2; ++half) {
                int ti = lane >> 3;
                int k = s*16 + (ti & 1)*8 + (lane & 7);
                int ng = ((wn*32 + half*16) >> 3) + (ti >> 1);
                uint32_t byt = (uint32_t)k*256 + (((ng ^ (k & 7)) & 15) << 4);
                ldsm4t(Bh + half*4, sb + XH + byt);
                ldsm4t(Bl + half*4, sb + XL + byt);
            }
            #pragma unroll
            for (int mf = 0; mf < 2; ++mf)
                #pragma unroll
                for (int nf = 0; nf < 4; ++nf) {
                    mma_bf16(acc[mf][nf], Ah + mf*4, Bh + nf*2);
                    mma_bf16(acc[mf][nf], Al + mf*4, Bh + nf*2);
                    mma_bf16(acc[mf][nf], Ah + mf*4, Bl + nf*2);
                }
        }
        CPA_WAIT0();
        __syncthreads();   // stage(next) ready; all ldsm of X done

        // ---- epilogue: bias, store Y3, stats ----
        #pragma unroll
        for (int mf = 0; mf < 2; ++mf) {
            int r = wm*32 + mf*16 + (lane >> 2);
            float b0 = bs[mf*2], b1 = bs[mf*2 + 1];
            float s10 = 0.f, s20 = 0.f, s11 = 0.f, s21 = 0.f;
            #pragma unroll
            for (int nf = 0; nf < 4; ++nf) {
                int col = p0 + wn*32 + nf*8 + 2*(lane & 3);
                float y0 = acc[mf][nf][0] + b0, y1 = acc[mf][nf][1] + b0;
                float y2 = acc[mf][nf][2] + b1, y3 = acc[mf][nf][3] + b1;
                *(float2*)&g_Y3[(size_t)r*PP + col]       = make_float2(y0, y1);
                *(float2*)&g_Y3[(size_t)(r + 8)*PP + col] = make_float2(y2, y3);
                s10 += y0 + y1; s20 += y0*y0 + y1*y1;
                s11 += y2 + y3; s21 += y2*y2 + y3*y3;
            }
            #pragma unroll
            for (int off = 1; off <= 2; off <<= 1) {
                s10 += __shfl_xor_sync(0xffffffffu, s10, off);
                s20 += __shfl_xor_sync(0xffffffffu, s20, off);
                s11 += __shfl_xor_sync(0xffffffffu, s11, off);
                s21 += __shfl_xor_sync(0xffffffffu, s21, off);
            }
            if ((lane & 3) == 0) {
                d1a[mf*2]   += (double)s10; d2a[mf*2]   += (double)s20;
                d1a[mf*2+1] += (double)s11; d2a[mf*2+1] += (double)s21;
            }
        }
    }

    if ((lane & 3) == 0) {
        #pragma unroll
        for (int q = 0; q < 4; ++q) {
            int r = wm*32 + (q >> 1)*16 + (q & 1)*8 + (lane >> 2);
            atomicAdd(&g_sum[2][r], d1a[q]);
            atomicAdd(&g_sq [2][r], d2a[q]);
        }
    }
}

// ===========================================================================
// h_fl2: pipelined warp-MMA bf16-split GEMM, layer 3 (128->256), N-tile 64.
// smem: Xh@0 Xl@16K Wh@32K Wl@96K | stage@160K (128 rows x 272B) | misc.
// Epilogue: per-lane k-group max/min (no Y4).
// ===========================================================================
#define FL2_STRIDE 272
#define FL2_STAGE  163840
#define FL2_MISC   (163840 + 128*FL2_STRIDE)
#define FL2_SMEM   (FL2_MISC + 1024)
__global__ void __launch_bounds__(512) h_fl2(const float* __restrict__ W,
                                             const float* __restrict__ bias)
{
    extern __shared__ char smem[];
    const uint32_t XH = 0, XL = 16384, WH = 32768, WL = 98304;
    float* sSc = (float*)(smem + FL2_MISC);
    float* sSh = (float*)(smem + FL2_MISC + 512);
    uint32_t sb = smem_u32(smem);

    int tid = threadIdx.x, lane = tid & 31, wid = tid >> 5;
    int wm = wid >> 1, wn = wid & 1;

    if (tid < 128) { sSc[tid] = g_scale[2][tid]; sSh[tid] = g_shift[2][tid]; }

    // W2 (256x128) -> smem bf16 hi/lo
    {
        int o = tid >> 1, c0 = (tid & 1) * 64;
        const float* wr = W + o*128 + c0;
        uint32_t rowb = (uint32_t)o * 256;
        #pragma unroll
        for (int j = 0; j < 32; ++j) {
            int c = c0 + 2*j;
            float ra, rb;
            uint32_t hi = pack_hi2(wr[2*j], wr[2*j+1], ra, rb);
            uint32_t lo = pack2(ra, rb);
            uint32_t byt = rowb + ((((c >> 3) ^ (o & 7)) & 15) << 4) + (c & 7)*2;
            *(uint32_t*)(smem + WH + byt) = hi;
            *(uint32_t*)(smem + WL + byt) = lo;
        }
    }

    int fc  = tid >> 2;              // 0..127 channel
    int fn0 = (tid & 3) * 16;        // 0/16/32/48
    uint32_t sdst = sb + FL2_STAGE + (uint32_t)fc*FL2_STRIDE + (uint32_t)fn0*4;

    int r0 = wm*32 + (lane >> 2);
    float bs[4] = { bias[r0], bias[r0 + 8], bias[r0 + 16], bias[r0 + 24] };
    double d1a[4] = {0,0,0,0}, d2a[4] = {0,0,0,0};

    // ---- prologue ----
    int tile0 = blockIdx.x;
    if (tile0 < PP/64) {
        const float* src = &g_Y3[(size_t)fc*PP + tile0*64 + fn0];
        #pragma unroll
        for (int j = 0; j < 4; ++j) cpa16(sdst + j*16, src + j*4);
    }
    CPA_COMMIT(); CPA_WAIT0();
    __syncthreads();

    for (int tile = tile0; tile < PP/64; tile += gridDim.x) {
        // ---- pack stage -> XH/XL with BN+relu ----
        {
            const float* sv = (const float*)(smem + FL2_STAGE + (size_t)fc*FL2_STRIDE) + fn0;
            float scv = sSc[fc], shv = sSh[fc];
            uint32_t rowb = (uint32_t)fc * 128;
            #pragma unroll
            for (int j = 0; j < 4; ++j) {
                float4 r = ((const float4*)sv)[j];
                float v0 = fmaxf(fmaf(r.x, scv, shv), 0.f);
                float v1 = fmaxf(fmaf(r.y, scv, shv), 0.f);
                float v2 = fmaxf(fmaf(r.z, scv, shv), 0.f);
                float v3 = fmaxf(fmaf(r.w, scv, shv), 0.f);
                int n = fn0 + 4*j;
                float ra, rb;
                uint32_t h0 = pack_hi2(v0, v1, ra, rb);
                uint32_t l0 = pack2(ra, rb);
                uint32_t h1 = pack_hi2(v2, v3, ra, rb);
                uint32_t l1 = pack2(ra, rb);
                uint32_t by0 = rowb + ((((n >> 3) ^ (fc & 7)) & 7) << 4) + (n & 7)*2;
                int n2 = n + 2;
                uint32_t by1 = rowb + ((((n2 >> 3) ^ (fc & 7)) & 7) << 4) + (n2 & 7)*2;
                *(uint32_t*)(smem + XH + by0) = h0;
                *(uint32_t*)(smem + XL + by0) = l0;
                *(uint32_t*)(smem + XH + by1) = h1;
                *(uint32_t*)(smem + XL + by1) = l1;
            }
        }
        __syncthreads();

        // ---- prefetch next ----
        int nxt = tile + gridDim.x;
        if (nxt < PP/64) {
            const float* src = &g_Y3[(size_t)fc*PP + nxt*64 + fn0];
            #pragma unroll
            for (int j = 0; j < 4; ++j) cpa16(sdst + j*16, src + j*4);
        }
        CPA_COMMIT();

        // ---- MMA ----
        float acc[2][4][4];
        #pragma unroll
        for (int i = 0; i < 2; ++i)
            #pragma unroll
            for (int j = 0; j < 4; ++j)
                #pragma unroll
                for (int q = 0; q < 4; ++q) acc[i][j][q] = 0.f;

        #pragma unroll
        for (int s = 0; s < 8; ++s) {
            uint32_t Ah[8], Al[8], Bh[8], Bl[8];
            #pragma unroll
            for (int mf = 0; mf < 2; ++mf) {
                int rr = wm*32 + mf*16 + (lane & 15);
                uint32_t g = (uint32_t)(2*s + (lane >> 4));
                uint32_t byt = (uint32_t)rr*256 + (((g ^ (rr & 7)) & 15) << 4);
                ldsm4(Ah + mf*4, sb + WH + byt);
                ldsm4(Al + mf*4, sb + WL + byt);
            }
            #pragma unroll
            for (int half = 0; half < 2; ++half) {
                int ti = lane >> 3;
                int k = s*16 + (ti & 1)*8 + (lane & 7);
                int ng = ((wn*32 + half*16) >> 3) + (ti >> 1);
                uint32_t byt = (uint32_t)k*128 + (((ng ^ (k & 7)) & 7) << 4);
                ldsm4t(Bh + half*4, sb + XH + byt);
                ldsm4t(Bl + half*4, sb + XL + byt);
            }
            #pragma unroll
            for (int mf = 0; mf < 2; ++mf)
                #pragma unroll
                for (int nf = 0; nf < 4; ++nf) {
                    mma_bf16(acc[mf][nf], Ah + mf*4, Bh + nf*2);
                    mma_bf16(acc[mf][nf], Al + mf*4, Bh + nf*2);
                    mma_bf16(acc[mf][nf], Ah + mf*4, Bl + nf*2);
                }
        }
        CPA_WAIT0();
        __syncthreads();

        // ---- epilogue: k-group max/min + stats ----
        int grp = tile*2 + wn;
        #pragma unroll
        for (int mf = 0; mf < 2; ++mf) {
            int r = wm*32 + mf*16 + (lane >> 2);
            float b0 = bs[mf*2], b1 = bs[mf*2 + 1];
            float mx0 = -1e30f, mn0 = 1e30f, mx1 = -1e30f, mn1 = 1e30f;
            float s10 = 0.f, s20 = 0.f, s11 = 0.f, s21 = 0.f;
            #pragma unroll
            for (int nf = 0; nf < 4; ++nf) {
                float y0 = acc[mf][nf][0] + b0, y1 = acc[mf][nf][1] + b0;
                float y2 = acc[mf][nf][2] + b1, y3 = acc[mf][nf][3] + b1;
                mx0 = fmaxf(mx0, fmaxf(y0, y1)); mn0 = fminf(mn0, fminf(y0, y1));
                mx1 = fmaxf(mx1, fmaxf(y2, y3)); mn1 = fminf(mn1, fminf(y2, y3));
                s10 += y0 + y1; s20 += y0*y0 + y1*y1;
                s11 += y2 + y3; s21 += y2*y2 + y3*y3;
            }
            #pragma unroll
            for (int off = 1; off <= 2; off <<= 1) {
                mx0 = fmaxf(mx0, __shfl_xor_sync(0xffffffffu, mx0, off));
                mn0 = fminf(mn0, __shfl_xor_sync(0xffffffffu, mn0, off));
                mx1 = fmaxf(mx1, __shfl_xor_sync(0xffffffffu, mx1, off));
                mn1 = fminf(mn1, __shfl_xor_sync(0xffffffffu, mn1, off));
                s10 += __shfl_xor_sync(0xffffffffu, s10, off);
                s20 += __shfl_xor_sync(0xffffffffu, s20, off);
                s11 += __shfl_xor_sync(0xffffffffu, s11, off);
                s21 += __shfl_xor_sync(0xffffffffu, s21, off);
            }
            if ((lane & 3) == 0) {
                g_mx[(size_t)r*NG + grp]       = mx0;
                g_mn[(size_t)r*NG + grp]       = mn0;
                g_mx[(size_t)(r + 8)*NG + grp] = mx1;
                g_mn[(size_t)(r + 8)*NG + grp] = mn1;
                d1a[mf*2]   += (double)s10; d2a[mf*2]   += (double)s20;
                d1a[mf*2+1] += (double)s11; d2a[mf*2+1] += (double)s21;
            }
        }
    }

    if ((lane & 3) == 0) {
        #pragma unroll
        for (int q = 0; q < 4; ++q) {
            int r = wm*32 + (q >> 1)*16 + (q & 1)*8 + (lane >> 2);
            atomicAdd(&g_sum[3][r], d1a[q]);
            atomicAdd(&g_sq [3][r], d2a[q]);
        }
    }
}

// ---------------------------------------------------------------------------
__global__ void k_finalize(int layer, const float* __restrict__ gamma,
                           const float* __restrict__ beta, int cout)
{
    int c = threadIdx.x;
    if (c < cout) {
        double mean = g_sum[layer][c] / (double)PP;
        double var  = g_sq [layer][c] / (double)PP - mean*mean;
        double invs = rsqrt(var + 1e-5);
        double sc   = (double)gamma[c] * invs;
        g_scale[layer][c] = (float)sc;
        g_shift[layer][c] = (float)((double)beta[c] - mean * sc);
    }
}

// ---------------------------------------------------------------------------
__global__ void __launch_bounds__(256) k_out(float* __restrict__ out)
{
    int t = blockIdx.x * blockDim.x + threadIdx.x;
    if (t >= Bc*256*Sc) return;
    int s = t & (Sc - 1);
    int o = (t >> 11) & 255;
    int b = t >> 19;
    float sc = g_scale[3][o], sh = g_shift[3][o];
    int grp = b*Sc + s;
    float v = (sc > 0.f) ? g_mx[(size_t)o*NG + grp] : g_mn[(size_t)o*NG + grp];
    out[2*Bc*Sc*3 + t] = fmaxf(fmaf(v, sc, sh), 0.f);
}

// ---------------------------------------------------------------------------
extern "C" void kernel_launch(void* const* d_in, const int* in_sizes, int n_in,
                              void* d_out, int out_size)
{
    const float* contour = (const float*)d_in[0];
    const float* loa     = (const float*)d_in[1];
    const float* fmaps   = (const float*)d_in[2];
    const float* fe_w1   = (const float*)d_in[3];
    const float* fe_b1   = (const float*)d_in[4];
    const float* fe_g1   = (const float*)d_in[5];
    const float* fe_be1  = (const float*)d_in[6];
    const float* fe_w2   = (const float*)d_in[7];
    const float* fe_b2   = (const float*)d_in[8];
    const float* fe_g2   = (const float*)d_in[9];
    const float* fe_be2  = (const float*)d_in[10];
    const float* fl_w1   = (const float*)d_in[11];
    const float* fl_b1   = (const float*)d_in[12];
    const float* fl_g1   = (const float*)d_in[13];
    const float* fl_be1  = (const float*)d_in[14];
    const float* fl_w2   = (const float*)d_in[15];
    const float* fl_b2   = (const float*)d_in[16];
    const float* fl_g2   = (const float*)d_in[17];
    const float* fl_be2  = (const float*)d_in[18];
    float* out = (float*)d_out;

    cudaFuncSetAttribute(h_fl1, cudaFuncAttributeMaxDynamicSharedMemorySize, FL1_SMEM);
    cudaFuncSetAttribute(h_fl2, cudaFuncAttributeMaxDynamicSharedMemorySize, FL2_SMEM);

    const int PBLK = PP / 128;   // 4096

    k_rif<<<Bc*Sc/8, 256>>>(contour, loa, out);

    k_conv<8,   32,  32, 0, 0><<<dim3(PBLK, 1), 256>>>(fe_w1, fe_b1);
    k_finalize<<<1, 256>>>(0, fe_g1, fe_be1, 32);

    k_conv<32,  64,  64, 1, 1><<<dim3(PBLK, 1), 256>>>(fe_w2, fe_b2);
    k_finalize<<<1, 256>>>(1, fe_g2, fe_be2, 64);

    h_fl1<<<148, 512, FL1_SMEM>>>(fl_w1, fl_b1, fmaps);
    k_finalize<<<1, 256>>>(2, fl_g1, fl_be1, 128);

    h_fl2<<<148, 512, FL2_SMEM>>>(fl_w2, fl_b2);
    k_finalize<<<1, 256>>>(3, fl_g2, fl_be2, 256);

    k_out<<<(Bc*256*Sc + 255)/256, 256>>>(out);
}

// round 13
// speedup vs baseline: 1.2612x; 1.2612x over previous
#include <cuda_runtime.h>
#include <cuda_bf16.h>
#include <cuda_fp16.h>
#include <math.h>
#include <stdint.h>

#define Bc 8
#define Nn 8192
#define Sc 2048
#define Kc 32
#define Dc 64
#define PP (Bc*Sc*Kc)   // 524288 positions
#define NG (PP/32)      // 16384 k-groups

// ---------------- scratch ---------------------------------------------------
__device__ float g_X0[8   * PP];
__device__ float g_Y1[32  * PP];
__device__ float g_Y2[64  * PP];
__device__ float g_Y3[128 * PP];
__device__ float g_mx[256 * NG];
__device__ float g_mn[256 * NG];
__device__ int   g_gidx[Sc*Kc];
__device__ double g_sum[4][256];
__device__ double g_sq [4][256];
__device__ float g_scale[4][256];
__device__ float g_shift[4][256];

__device__ __forceinline__ float clamp_ac(float x) {
    return fminf(fmaxf(x, -0.9999999f), 0.9999999f);
}

// =================== warp MMA helpers (baseline PTX) =======================
__device__ __forceinline__ uint32_t smem_u32(const void* p) {
    uint32_t a;
    asm("{ .reg .u64 t; cvta.to.shared.u64 t, %1; cvt.u32.u64 %0, t; }"
        : "=r"(a) : "l"(p));
    return a;
}
__device__ __forceinline__ void ldsm4(uint32_t* r, uint32_t a) {
    asm volatile("ldmatrix.sync.aligned.m8n8.x4.shared.b16 {%0,%1,%2,%3}, [%4];"
        : "=r"(r[0]), "=r"(r[1]), "=r"(r[2]), "=r"(r[3]) : "r"(a));
}
__device__ __forceinline__ void ldsm4t(uint32_t* r, uint32_t a) {
    asm volatile("ldmatrix.sync.aligned.m8n8.x4.trans.shared.b16 {%0,%1,%2,%3}, [%4];"
        : "=r"(r[0]), "=r"(r[1]), "=r"(r[2]), "=r"(r[3]) : "r"(a));
}
__device__ __forceinline__ void mma_fp16(float* d, const uint32_t* a, const uint32_t* b) {
    asm volatile("mma.sync.aligned.m16n8k16.row.col.f32.f16.f16.f32 "
        "{%0,%1,%2,%3}, {%4,%5,%6,%7}, {%8,%9}, {%0,%1,%2,%3};"
        : "+f"(d[0]), "+f"(d[1]), "+f"(d[2]), "+f"(d[3])
        : "r"(a[0]), "r"(a[1]), "r"(a[2]), "r"(a[3]), "r"(b[0]), "r"(b[1]));
}
// pack two f32 -> f16x2 (lo = a, hi = b)
__device__ __forceinline__ uint32_t packh2(float a, float b) {
    uint32_t r;
    asm("cvt.rn.f16x2.f32 %0, %1, %2;" : "=r"(r) : "f"(b), "f"(a));
    return r;
}

// ---------------------------------------------------------------------------
// k_rif: unchanged (passing since R5).
// ---------------------------------------------------------------------------
__global__ void __launch_bounds__(256) k_rif(const float* __restrict__ contour,
                                             const float* __restrict__ loa,
                                             float* __restrict__ out)
{
    const unsigned FULL = 0xffffffffu;
    int tid  = threadIdx.x;
    if (blockIdx.x == 0) {
        #pragma unroll
        for (int j = 0; j < 4; ++j) {
            ((double*)g_sum)[tid + j*256] = 0.0;
            ((double*)g_sq )[tid + j*256] = 0.0;
        }
    }
    int w    = blockIdx.x * 8 + (tid >> 5);
    int lane = tid & 31;
    int b = w >> 11;
    int s = w & (Sc - 1);

    int i0;
    if (s == Sc - 1) i0 = Nn - 1;
    else {
        float t = __fdiv_rn((float)s, 2047.0f);
        float v = __fmul_rn(8191.0f, t);
        i0 = (int)v;
    }
    int n = (i0 - (Kc/2) + lane) & (Nn - 1);
    if (b == 0) g_gidx[s*Kc + lane] = n;

    const float* cp = contour + ((size_t)b*Nn + i0)*3;
    float spx = cp[0], spy = cp[1], spz = cp[2];
    const float* ap = loa + ((size_t)b*Nn + i0)*3;
    float ax = ap[0], ay = ap[1], az = ap[2];

    if (lane < 3) {
        out[(b*Sc + s)*3 + lane]           = cp[lane];
        out[Bc*Sc*3 + (b*Sc + s)*3 + lane] = ap[lane];
    }

    const float* pp_ = contour + ((size_t)b*Nn + n)*3;
    float lx = pp_[0] - spx, ly = pp_[1] - spy, lz = pp_[2] - spz;
    const float* lp = loa + ((size_t)b*Nn + n)*3;
    float nlx = lp[0], nly = lp[1], nlz = lp[2];

    float sq = lx*lx + ly*ly + lz*lz;
    float d1 = (sq > 0.f) ? sqrtf(sq) : 0.f;
    float inv = (d1 > 0.f) ? (1.f / d1) : 0.f;
    float ux = lx*inv, uy = ly*inv, uz = lz*inv;

    int pl = (lane + 31) & 31;
    float plx = __shfl_sync(FULL, lx, pl);
    float ply = __shfl_sync(FULL, ly, pl);
    float plz = __shfl_sync(FULL, lz, pl);
    float pnlx = __shfl_sync(FULL, nlx, pl);
    float pnly = __shfl_sync(FULL, nly, pl);
    float pnlz = __shfl_sync(FULL, nlz, pl);
    float pux = __shfl_sync(FULL, ux, pl);
    float puy = __shfl_sync(FULL, uy, pl);
    float puz = __shfl_sync(FULL, uz, pl);

    float ivx = lx - plx, ivy = ly - ply, ivz = lz - plz;
    float isq = ivx*ivx + ivy*ivy + ivz*ivz;
    float idn = (isq > 0.f) ? sqrtf(isq) : 0.f;
    float ii  = (idn > 0.f) ? (1.f / idn) : 0.f;
    float iux = ivx*ii, iuy = ivy*ii, iuz = ivz*ii;

    float a1 = ux*ax + uy*ay + uz*az;
    float a2 = ux*nlx + uy*nly + uz*nlz;
    float a3 = acosf(clamp_ac(nlx*ax + nly*ay + nlz*az));
    float a4 = iux*nlx + iuy*nly + iuz*nlz;
    float a5 = iux*pnlx + iuy*pnly + iuz*pnlz;
    float a6 = acosf(clamp_ac(nlx*pnlx + nly*pnly + nlz*pnlz));
    float d2 = acosf(clamp_ac(ux*pux + uy*puy + uz*puz));

    size_t p = (size_t)(b*Sc + s)*Kc + lane;
    g_X0[0*(size_t)PP + p] = d1;
    g_X0[1*(size_t)PP + p] = d2;
    g_X0[2*(size_t)PP + p] = a1;
    g_X0[3*(size_t)PP + p] = a2;
    g_X0[4*(size_t)PP + p] = a3;
    g_X0[5*(size_t)PP + p] = a4;
    g_X0[6*(size_t)PP + p] = a5;
    g_X0[7*(size_t)PP + p] = a6;
}

// ---------------------------------------------------------------------------
// FFMA conv for small layers 0 (8->32) and 1 (32->64). Unchanged (passing).
// ---------------------------------------------------------------------------
template<int CIN, int COUT, int TILE_O, int MODE, int LAYER>
__global__ void __launch_bounds__(256) k_conv(const float* __restrict__ W,
                                              const float* __restrict__ bias)
{
    constexpr int OW = TILE_O / 16;
    constexpr int PL = (LAYER > 0) ? (LAYER - 1) : 0;

    const float* Xin  = (LAYER == 0) ? g_X0 : g_Y1;
    float*       Yout = (LAYER == 0) ? g_Y1 : g_Y2;

    __shared__ __align__(16) float sW[8][TILE_O];
    __shared__ __align__(16) float sX[8][128];
    __shared__ float sSc[CIN];
    __shared__ float sSh[CIN];

    int tid = threadIdx.x;
    int o0  = blockIdx.y * TILE_O;
    int p0  = blockIdx.x * 128;

    if (MODE >= 1) {
        if (tid < CIN) { sSc[tid] = g_scale[PL][tid]; sSh[tid] = g_shift[PL][tid]; }
    }
    __syncthreads();

    int tx = tid & 15, ty = tid >> 4;
    int kcl = tid >> 5;
    int pp4 = (tid & 31) * 4;

    float acc[OW][8];
    #pragma unroll
    for (int i = 0; i < OW; ++i)
        #pragma unroll
        for (int j = 0; j < 8; ++j) acc[i][j] = 0.f;

    #pragma unroll 1
    for (int cc = 0; cc < CIN/8; ++cc) {
        int c0 = cc * 8;
        for (int idx = tid; idx < TILE_O*8; idx += 256) {
            int o = idx & (TILE_O - 1), c = idx / TILE_O;
            sW[c][o] = W[(o0 + o)*CIN + c0 + c];
        }
        {
            int c = c0 + kcl;
            float4 v;
            if (MODE == 0) {
                v = *(const float4*)&Xin[(size_t)c*PP + p0 + pp4];
            } else {
                float4 r = *(const float4*)&Xin[(size_t)c*PP + p0 + pp4];
                float scv = sSc[c], shv = sSh[c];
                v.x = fmaxf(fmaf(r.x, scv, shv), 0.f);
                v.y = fmaxf(fmaf(r.y, scv, shv), 0.f);
                v.z = fmaxf(fmaf(r.z, scv, shv), 0.f);
                v.w = fmaxf(fmaf(r.w, scv, shv), 0.f);
            }
            *(float4*)&sX[kcl][pp4] = v;
        }
        __syncthreads();

        #pragma unroll
        for (int kc = 0; kc < 8; ++kc) {
            float4 xa = ((const float4*)sX[kc])[tx*2];
            float4 xb = ((const float4*)sX[kc])[tx*2 + 1];
            float xr[8] = {xa.x, xa.y, xa.z, xa.w, xb.x, xb.y, xb.z, xb.w};
            float wr[OW];
            if constexpr (OW == 4) {
                float4 wa = ((const float4*)sW[kc])[ty];
                wr[0]=wa.x; wr[1]=wa.y; wr[2]=wa.z; wr[3]=wa.w;
            } else {
                #pragma unroll
                for (int i = 0; i < OW; ++i) wr[i] = sW[kc][ty*OW + i];
            }
            #pragma unroll
            for (int i = 0; i < OW; ++i)
                #pragma unroll
                for (int j = 0; j < 8; ++j)
                    acc[i][j] = fmaf(wr[i], xr[j], acc[i][j]);
        }
        __syncthreads();
    }

    #pragma unroll
    for (int i = 0; i < OW; ++i) {
        int o = o0 + ty*OW + i;
        float bo = bias[o];
        float y[8];
        #pragma unroll
        for (int j = 0; j < 8; ++j) y[j] = acc[i][j] + bo;

        *(float4*)&Yout[(size_t)o*PP + p0 + tx*8]     = make_float4(y[0], y[1], y[2], y[3]);
        *(float4*)&Yout[(size_t)o*PP + p0 + tx*8 + 4] = make_float4(y[4], y[5], y[6], y[7]);

        float s1 = 0.f, s2 = 0.f;
        #pragma unroll
        for (int j = 0; j < 8; ++j) { s1 += y[j]; s2 += y[j]*y[j]; }
        #pragma unroll
        for (int off = 1; off <= 8; off <<= 1) {
            s1 += __shfl_xor_sync(0xffffffffu, s1, off);
            s2 += __shfl_xor_sync(0xffffffffu, s2, off);
        }
        if (tx == 0) {
            atomicAdd(&g_sum[LAYER][o], (double)s1);
            atomicAdd(&g_sq [LAYER][o], (double)s2);
        }
    }
}

// ===========================================================================
// h_fl1: single-term fp16 warp-MMA GEMM, layer 2 (128->128), N-tile 128.
// smem: X@0 (32K, f16 rows 256B) W@32768 (32K) misc@65536.
// 512 thr, warps 4(m)x4(n), warp tile 32x32.
// ===========================================================================
#define FL1_SMEM (65536 + 1024)
__global__ void __launch_bounds__(512) h_fl1(const float* __restrict__ W,
                                             const float* __restrict__ bias,
                                             const float* __restrict__ fmaps)
{
    extern __shared__ char smem[];
    const uint32_t XH = 0, WH = 32768, MISC = 65536;
    float* sSc = (float*)(smem + MISC);
    float* sSh = (float*)(smem + MISC + 256);
    uint32_t sb = smem_u32(smem);

    int tid = threadIdx.x, lane = tid & 31, wid = tid >> 5;
    int wm = wid & 3, wn = wid >> 2;

    if (tid < 64) { sSc[tid] = g_scale[1][tid]; sSh[tid] = g_shift[1][tid]; }

    // W -> smem fp16, swizzled rows of 256B
    {
        int o = tid >> 2, c0 = (tid & 3) * 32;
        const float* wr = W + o*128 + c0;
        uint32_t rowb = (uint32_t)o * 256;
        #pragma unroll
        for (int j = 0; j < 16; ++j) {
            int c = c0 + 2*j;
            uint32_t h = packh2(wr[2*j], wr[2*j+1]);
            uint32_t byt = rowb + ((((c >> 3) ^ (o & 7)) & 15) << 4) + (c & 7)*2;
            *(uint32_t*)(smem + WH + byt) = h;
        }
    }

    int fc  = tid >> 2;              // 0..127 channel
    int fn0 = (tid & 3) * 32;        // 0/32/64/96 position offset

    int r0 = wm*32 + (lane >> 2);
    float bs[4] = { bias[r0], bias[r0 + 8], bias[r0 + 16], bias[r0 + 24] };
    double d1a[4] = {0,0,0,0}, d2a[4] = {0,0,0,0};
    __syncthreads();

    for (int tile = blockIdx.x; tile < PP/128; tile += gridDim.x) {
        int p0 = tile * 128, bb = p0 >> 16;
        __syncthreads();   // prev iter's ldsm reads done before overwriting X

        // ---- fill X: bn_relu(Y2) for c<64, fmaps gather for c>=64 ----
        {
            float v[32];
            if (fc < 64) {
                const float4* src = (const float4*)&g_Y2[(size_t)fc*PP + p0 + fn0];
                float scv = sSc[fc], shv = sSh[fc];
                #pragma unroll
                for (int j = 0; j < 8; ++j) {
                    float4 r = src[j];
                    v[4*j+0] = fmaxf(fmaf(r.x, scv, shv), 0.f);
                    v[4*j+1] = fmaxf(fmaf(r.y, scv, shv), 0.f);
                    v[4*j+2] = fmaxf(fmaf(r.z, scv, shv), 0.f);
                    v[4*j+3] = fmaxf(fmaf(r.w, scv, shv), 0.f);
                }
            } else {
                const float* fp = fmaps + ((size_t)bb*Dc + (fc - 64))*Nn;
                const int4* gi = (const int4*)&g_gidx[(p0 & 65535) + fn0];
                #pragma unroll
                for (int j = 0; j < 8; ++j) {
                    int4 ix = gi[j];
                    v[4*j+0] = fp[ix.x];
                    v[4*j+1] = fp[ix.y];
                    v[4*j+2] = fp[ix.z];
                    v[4*j+3] = fp[ix.w];
                }
            }
            uint32_t rowb = (uint32_t)fc * 256;
            #pragma unroll
            for (int j = 0; j < 16; ++j) {
                int n = fn0 + 2*j;
                uint32_t h = packh2(v[2*j], v[2*j+1]);
                uint32_t byt = rowb + ((((n >> 3) ^ (fc & 7)) & 15) << 4) + (n & 7)*2;
                *(uint32_t*)(smem + XH + byt) = h;
            }
        }
        __syncthreads();

        // ---- MMA (single term) ----
        float acc[2][4][4];
        #pragma unroll
        for (int i = 0; i < 2; ++i)
            #pragma unroll
            for (int j = 0; j < 4; ++j)
                #pragma unroll
                for (int q = 0; q < 4; ++q) acc[i][j][q] = 0.f;

        #pragma unroll
        for (int s = 0; s < 8; ++s) {
            uint32_t A[8], B[8];
            #pragma unroll
            for (int mf = 0; mf < 2; ++mf) {
                int rr = wm*32 + mf*16 + (lane & 15);
                uint32_t g = (uint32_t)(2*s + (lane >> 4));
                uint32_t byt = (uint32_t)rr*256 + (((g ^ (rr & 7)) & 15) << 4);
                ldsm4(A + mf*4, sb + WH + byt);
            }
            #pragma unroll
            for (int half = 0; half < 2; ++half) {
                int ti = lane >> 3;
                int k = s*16 + (ti & 1)*8 + (lane & 7);
                int ng = ((wn*32 + half*16) >> 3) + (ti >> 1);
                uint32_t byt = (uint32_t)k*256 + (((ng ^ (k & 7)) & 15) << 4);
                ldsm4t(B + half*4, sb + XH + byt);
            }
            #pragma unroll
            for (int mf = 0; mf < 2; ++mf)
                #pragma unroll
                for (int nf = 0; nf < 4; ++nf)
                    mma_fp16(acc[mf][nf], A + mf*4, B + nf*2);
        }

        // ---- epilogue: bias, store Y3, stats ----
        #pragma unroll
        for (int mf = 0; mf < 2; ++mf) {
            int r = wm*32 + mf*16 + (lane >> 2);
            float b0 = bs[mf*2], b1 = bs[mf*2 + 1];
            float s10 = 0.f, s20 = 0.f, s11 = 0.f, s21 = 0.f;
            #pragma unroll
            for (int nf = 0; nf < 4; ++nf) {
                int col = p0 + wn*32 + nf*8 + 2*(lane & 3);
                float y0 = acc[mf][nf][0] + b0, y1 = acc[mf][nf][1] + b0;
                float y2 = acc[mf][nf][2] + b1, y3 = acc[mf][nf][3] + b1;
                *(float2*)&g_Y3[(size_t)r*PP + col]       = make_float2(y0, y1);
                *(float2*)&g_Y3[(size_t)(r + 8)*PP + col] = make_float2(y2, y3);
                s10 += y0 + y1; s20 += y0*y0 + y1*y1;
                s11 += y2 + y3; s21 += y2*y2 + y3*y3;
            }
            #pragma unroll
            for (int off = 1; off <= 2; off <<= 1) {
                s10 += __shfl_xor_sync(0xffffffffu, s10, off);
                s20 += __shfl_xor_sync(0xffffffffu, s20, off);
                s11 += __shfl_xor_sync(0xffffffffu, s11, off);
                s21 += __shfl_xor_sync(0xffffffffu, s21, off);
            }
            if ((lane & 3) == 0) {
                d1a[mf*2]   += (double)s10; d2a[mf*2]   += (double)s20;
                d1a[mf*2+1] += (double)s11; d2a[mf*2+1] += (double)s21;
            }
        }
    }

    if ((lane & 3) == 0) {
        #pragma unroll
        for (int q = 0; q < 4; ++q) {
            int r = wm*32 + (q >> 1)*16 + (q & 1)*8 + (lane >> 2);
            atomicAdd(&g_sum[2][r], d1a[q]);
            atomicAdd(&g_sq [2][r], d2a[q]);
        }
    }
}

// ===========================================================================
// h_fl2: single-term fp16 warp-MMA GEMM, layer 3 (128->256), N-tile 64.
// smem: X@0 (16K, 128B rows) W@16384 (64K, 256B rows) misc@81920.
// 512 thr, warps 8(m)x2(n), warp tile 32x32.
// Epilogue: per-lane k-group max/min (no Y4).
// ===========================================================================
#define FL2_SMEM (81920 + 1024)
__global__ void __launch_bounds__(512) h_fl2(const float* __restrict__ W,
                                             const float* __restrict__ bias)
{
    extern __shared__ char smem[];
    const uint32_t XH = 0, WH = 16384, MISC = 81920;
    float* sSc = (float*)(smem + MISC);
    float* sSh = (float*)(smem + MISC + 512);
    uint32_t sb = smem_u32(smem);

    int tid = threadIdx.x, lane = tid & 31, wid = tid >> 5;
    int wm = wid >> 1, wn = wid & 1;

    if (tid < 128) { sSc[tid] = g_scale[2][tid]; sSh[tid] = g_shift[2][tid]; }

    // W2 (256x128) -> smem fp16, 256B rows
    {
        int o = tid >> 1, c0 = (tid & 1) * 64;
        const float* wr = W + o*128 + c0;
        uint32_t rowb = (uint32_t)o * 256;
        #pragma unroll
        for (int j = 0; j < 32; ++j) {
            int c = c0 + 2*j;
            uint32_t h = packh2(wr[2*j], wr[2*j+1]);
            uint32_t byt = rowb + ((((c >> 3) ^ (o & 7)) & 15) << 4) + (c & 7)*2;
            *(uint32_t*)(smem + WH + byt) = h;
        }
    }

    int fc  = tid >> 2;              // 0..127 channel
    int fn0 = (tid & 3) * 16;        // 0/16/32/48

    int r0 = wm*32 + (lane >> 2);
    float bs[4] = { bias[r0], bias[r0 + 8], bias[r0 + 16], bias[r0 + 24] };
    double d1a[4] = {0,0,0,0}, d2a[4] = {0,0,0,0};
    __syncthreads();

    for (int tile = blockIdx.x; tile < PP/64; tile += gridDim.x) {
        int p0 = tile * 64;
        __syncthreads();

        // ---- fill X = bn_relu(Y3), 128B rows ----
        {
            const float4* src = (const float4*)&g_Y3[(size_t)fc*PP + p0 + fn0];
            float scv = sSc[fc], shv = sSh[fc];
            uint32_t rowb = (uint32_t)fc * 128;
            #pragma unroll
            for (int j = 0; j < 4; ++j) {
                float4 r = src[j];
                float v0 = fmaxf(fmaf(r.x, scv, shv), 0.f);
                float v1 = fmaxf(fmaf(r.y, scv, shv), 0.f);
                float v2 = fmaxf(fmaf(r.z, scv, shv), 0.f);
                float v3 = fmaxf(fmaf(r.w, scv, shv), 0.f);
                int n = fn0 + 4*j;
                uint32_t h0 = packh2(v0, v1);
                uint32_t h1 = packh2(v2, v3);
                uint32_t by0 = rowb + ((((n >> 3) ^ (fc & 7)) & 7) << 4) + (n & 7)*2;
                int n2 = n + 2;
                uint32_t by1 = rowb + ((((n2 >> 3) ^ (fc & 7)) & 7) << 4) + (n2 & 7)*2;
                *(uint32_t*)(smem + XH + by0) = h0;
                *(uint32_t*)(smem + XH + by1) = h1;
            }
        }
        __syncthreads();

        // ---- MMA (single term) ----
        float acc[2][4][4];
        #pragma unroll
        for (int i = 0; i < 2; ++i)
            #pragma unroll
            for (int j = 0; j < 4; ++j)
                #pragma unroll
                for (int q = 0; q < 4; ++q) acc[i][j][q] = 0.f;

        #pragma unroll
        for (int s = 0; s < 8; ++s) {
            uint32_t A[8], B[8];
            #pragma unroll
            for (int mf = 0; mf < 2; ++mf) {
                int rr = wm*32 + mf*16 + (lane & 15);
                uint32_t g = (uint32_t)(2*s + (lane >> 4));
                uint32_t byt = (uint32_t)rr*256 + (((g ^ (rr & 7)) & 15) << 4);
                ldsm4(A + mf*4, sb + WH + byt);
            }
            #pragma unroll
            for (int half = 0; half < 2; ++half) {
                int ti = lane >> 3;
                int k = s*16 + (ti & 1)*8 + (lane & 7);
                int ng = ((wn*32 + half*16) >> 3) + (ti >> 1);
                uint32_t byt = (uint32_t)k*128 + (((ng ^ (k & 7)) & 7) << 4);
                ldsm4t(B + half*4, sb + XH + byt);
            }
            #pragma unroll
            for (int mf = 0; mf < 2; ++mf)
                #pragma unroll
                for (int nf = 0; nf < 4; ++nf)
                    mma_fp16(acc[mf][nf], A + mf*4, B + nf*2);
        }

        // ---- epilogue: k-group max/min + stats ----
        int grp = tile*2 + wn;
        #pragma unroll
        for (int mf = 0; mf < 2; ++mf) {
            int r = wm*32 + mf*16 + (lane >> 2);
            float b0 = bs[mf*2], b1 = bs[mf*2 + 1];
            float mx0 = -1e30f, mn0 = 1e30f, mx1 = -1e30f, mn1 = 1e30f;
            float s10 = 0.f, s20 = 0.f, s11 = 0.f, s21 = 0.f;
            #pragma unroll
            for (int nf = 0; nf < 4; ++nf) {
                float y0 = acc[mf][nf][0] + b0, y1 = acc[mf][nf][1] + b0;
                float y2 = acc[mf][nf][2] + b1, y3 = acc[mf][nf][3] + b1;
                mx0 = fmaxf(mx0, fmaxf(y0, y1)); mn0 = fminf(mn0, fminf(y0, y1));
                mx1 = fmaxf(mx1, fmaxf(y2, y3)); mn1 = fminf(mn1, fminf(y2, y3));
                s10 += y0 + y1; s20 += y0*y0 + y1*y1;
                s11 += y2 + y3; s21 += y2*y2 + y3*y3;
            }
            #pragma unroll
            for (int off = 1; off <= 2; off <<= 1) {
                mx0 = fmaxf(mx0, __shfl_xor_sync(0xffffffffu, mx0, off));
                mn0 = fminf(mn0, __shfl_xor_sync(0xffffffffu, mn0, off));
                mx1 = fmaxf(mx1, __shfl_xor_sync(0xffffffffu, mx1, off));
                mn1 = fminf(mn1, __shfl_xor_sync(0xffffffffu, mn1, off));
                s10 += __shfl_xor_sync(0xffffffffu, s10, off);
                s20 += __shfl_xor_sync(0xffffffffu, s20, off);
                s11 += __shfl_xor_sync(0xffffffffu, s11, off);
                s21 += __shfl_xor_sync(0xffffffffu, s21, off);
            }
            if ((lane & 3) == 0) {
                g_mx[(size_t)r*NG + grp]       = mx0;
                g_mn[(size_t)r*NG + grp]       = mn0;
                g_mx[(size_t)(r + 8)*NG + grp] = mx1;
                g_mn[(size_t)(r + 8)*NG + grp] = mn1;
                d1a[mf*2]   += (double)s10; d2a[mf*2]   += (double)s20;
                d1a[mf*2+1] += (double)s11; d2a[mf*2+1] += (double)s21;
            }
        }
    }

    if ((lane & 3) == 0) {
        #pragma unroll
        for (int q = 0; q < 4; ++q) {
            int r = wm*32 + (q >> 1)*16 + (q & 1)*8 + (lane >> 2);
            atomicAdd(&g_sum[3][r], d1a[q]);
            atomicAdd(&g_sq [3][r], d2a[q]);
        }
    }
}

// ---------------------------------------------------------------------------
__global__ void k_finalize(int layer, const float* __restrict__ gamma,
                           const float* __restrict__ beta, int cout)
{
    int c = threadIdx.x;
    if (c < cout) {
        double mean = g_sum[layer][c] / (double)PP;
        double var  = g_sq [layer][c] / (double)PP - mean*mean;
        double invs = rsqrt(var + 1e-5);
        double sc   = (double)gamma[c] * invs;
        g_scale[layer][c] = (float)sc;
        g_shift[layer][c] = (float)((double)beta[c] - mean * sc);
    }
}

// ---------------------------------------------------------------------------
__global__ void __launch_bounds__(256) k_out(float* __restrict__ out)
{
    int t = blockIdx.x * blockDim.x + threadIdx.x;
    if (t >= Bc*256*Sc) return;
    int s = t & (Sc - 1);
    int o = (t >> 11) & 255;
    int b = t >> 19;
    float sc = g_scale[3][o], sh = g_shift[3][o];
    int grp = b*Sc + s;
    float v = (sc > 0.f) ? g_mx[(size_t)o*NG + grp] : g_mn[(size_t)o*NG + grp];
    out[2*Bc*Sc*3 + t] = fmaxf(fmaf(v, sc, sh), 0.f);
}

// ---------------------------------------------------------------------------
extern "C" void kernel_launch(void* const* d_in, const int* in_sizes, int n_in,
                              void* d_out, int out_size)
{
    const float* contour = (const float*)d_in[0];
    const float* loa     = (const float*)d_in[1];
    const float* fmaps   = (const float*)d_in[2];
    const float* fe_w1   = (const float*)d_in[3];
    const float* fe_b1   = (const float*)d_in[4];
    const float* fe_g1   = (const float*)d_in[5];
    const float* fe_be1  = (const float*)d_in[6];
    const float* fe_w2   = (const float*)d_in[7];
    const float* fe_b2   = (const float*)d_in[8];
    const float* fe_g2   = (const float*)d_in[9];
    const float* fe_be2  = (const float*)d_in[10];
    const float* fl_w1   = (const float*)d_in[11];
    const float* fl_b1   = (const float*)d_in[12];
    const float* fl_g1   = (const float*)d_in[13];
    const float* fl_be1  = (const float*)d_in[14];
    const float* fl_w2   = (const float*)d_in[15];
    const float* fl_b2   = (const float*)d_in[16];
    const float* fl_g2   = (const float*)d_in[17];
    const float* fl_be2  = (const float*)d_in[18];
    float* out = (float*)d_out;

    cudaFuncSetAttribute(h_fl1, cudaFuncAttributeMaxDynamicSharedMemorySize, FL1_SMEM);
    cudaFuncSetAttribute(h_fl2, cudaFuncAttributeMaxDynamicSharedMemorySize, FL2_SMEM);

    const int PBLK = PP / 128;   // 4096

    k_rif<<<Bc*Sc/8, 256>>>(contour, loa, out);

    k_conv<8,   32,  32, 0, 0><<<dim3(PBLK, 1), 256>>>(fe_w1, fe_b1);
    k_finalize<<<1, 256>>>(0, fe_g1, fe_be1, 32);

    k_conv<32,  64,  64, 1, 1><<<dim3(PBLK, 1), 256>>>(fe_w2, fe_b2);
    k_finalize<<<1, 256>>>(1, fe_g2, fe_be2, 64);

    h_fl1<<<296, 512, FL1_SMEM>>>(fl_w1, fl_b1, fmaps);
    k_finalize<<<1, 256>>>(2, fl_g1, fl_be1, 128);

    h_fl2<<<296, 512, FL2_SMEM>>>(fl_w2, fl_b2);
    k_finalize<<<1, 256>>>(3, fl_g2, fl_be2, 256);

    k_out<<<(Bc*256*Sc + 255)/256, 256>>>(out);
}

// round 14
// speedup vs baseline: 1.3934x; 1.1049x over previous
#include <cuda_runtime.h>
#include <cuda_bf16.h>
#include <cuda_fp16.h>
#include <math.h>
#include <stdint.h>

#define Bc 8
#define Nn 8192
#define Sc 2048
#define Kc 32
#define Dc 64
#define PP (Bc*Sc*Kc)   // 524288 positions
#define NG (PP/32)      // 16384 k-groups

// ---------------- scratch ---------------------------------------------------
__device__ float g_X0[8   * PP];
__device__ float g_Y1[32  * PP];
__device__ float g_Y2[64  * PP];
__device__ float g_Y3[64  * PP];   // stored as __half[128*PP] (reinterpreted)
__device__ float g_mx[256 * NG];
__device__ float g_mn[256 * NG];
__device__ int   g_gidx[Sc*Kc];
__device__ double g_sum[4][256];
__device__ double g_sq [4][256];
__device__ float g_scale[4][256];
__device__ float g_shift[4][256];

__device__ __forceinline__ float clamp_ac(float x) {
    return fminf(fmaxf(x, -0.9999999f), 0.9999999f);
}

// =================== warp MMA helpers (baseline PTX) =======================
__device__ __forceinline__ uint32_t smem_u32(const void* p) {
    uint32_t a;
    asm("{ .reg .u64 t; cvta.to.shared.u64 t, %1; cvt.u32.u64 %0, t; }"
        : "=r"(a) : "l"(p));
    return a;
}
__device__ __forceinline__ void ldsm4(uint32_t* r, uint32_t a) {
    asm volatile("ldmatrix.sync.aligned.m8n8.x4.shared.b16 {%0,%1,%2,%3}, [%4];"
        : "=r"(r[0]), "=r"(r[1]), "=r"(r[2]), "=r"(r[3]) : "r"(a));
}
__device__ __forceinline__ void ldsm4t(uint32_t* r, uint32_t a) {
    asm volatile("ldmatrix.sync.aligned.m8n8.x4.trans.shared.b16 {%0,%1,%2,%3}, [%4];"
        : "=r"(r[0]), "=r"(r[1]), "=r"(r[2]), "=r"(r[3]) : "r"(a));
}
__device__ __forceinline__ void mma_fp16(float* d, const uint32_t* a, const uint32_t* b) {
    asm volatile("mma.sync.aligned.m16n8k16.row.col.f32.f16.f16.f32 "
        "{%0,%1,%2,%3}, {%4,%5,%6,%7}, {%8,%9}, {%0,%1,%2,%3};"
        : "+f"(d[0]), "+f"(d[1]), "+f"(d[2]), "+f"(d[3])
        : "r"(a[0]), "r"(a[1]), "r"(a[2]), "r"(a[3]), "r"(b[0]), "r"(b[1]));
}
// pack two f32 -> f16x2 (lo = a, hi = b)
__device__ __forceinline__ uint32_t packh2(float a, float b) {
    uint32_t r;
    asm("cvt.rn.f16x2.f32 %0, %1, %2;" : "=r"(r) : "f"(b), "f"(a));
    return r;
}
// unpack f16x2 -> two f32
__device__ __forceinline__ void unpackh2(uint32_t h, float& a, float& b) {
    __half2 v = *(__half2*)&h;
    float2 f = __half22float2(v);
    a = f.x; b = f.y;
}

// ---------------------------------------------------------------------------
// k_rif: unchanged (passing since R5).
// ---------------------------------------------------------------------------
__global__ void __launch_bounds__(256) k_rif(const float* __restrict__ contour,
                                             const float* __restrict__ loa,
                                             float* __restrict__ out)
{
    const unsigned FULL = 0xffffffffu;
    int tid  = threadIdx.x;
    if (blockIdx.x == 0) {
        #pragma unroll
        for (int j = 0; j < 4; ++j) {
            ((double*)g_sum)[tid + j*256] = 0.0;
            ((double*)g_sq )[tid + j*256] = 0.0;
        }
    }
    int w    = blockIdx.x * 8 + (tid >> 5);
    int lane = tid & 31;
    int b = w >> 11;
    int s = w & (Sc - 1);

    int i0;
    if (s == Sc - 1) i0 = Nn - 1;
    else {
        float t = __fdiv_rn((float)s, 2047.0f);
        float v = __fmul_rn(8191.0f, t);
        i0 = (int)v;
    }
    int n = (i0 - (Kc/2) + lane) & (Nn - 1);
    if (b == 0) g_gidx[s*Kc + lane] = n;

    const float* cp = contour + ((size_t)b*Nn + i0)*3;
    float spx = cp[0], spy = cp[1], spz = cp[2];
    const float* ap = loa + ((size_t)b*Nn + i0)*3;
    float ax = ap[0], ay = ap[1], az = ap[2];

    if (lane < 3) {
        out[(b*Sc + s)*3 + lane]           = cp[lane];
        out[Bc*Sc*3 + (b*Sc + s)*3 + lane] = ap[lane];
    }

    const float* pp_ = contour + ((size_t)b*Nn + n)*3;
    float lx = pp_[0] - spx, ly = pp_[1] - spy, lz = pp_[2] - spz;
    const float* lp = loa + ((size_t)b*Nn + n)*3;
    float nlx = lp[0], nly = lp[1], nlz = lp[2];

    float sq = lx*lx + ly*ly + lz*lz;
    float d1 = (sq > 0.f) ? sqrtf(sq) : 0.f;
    float inv = (d1 > 0.f) ? (1.f / d1) : 0.f;
    float ux = lx*inv, uy = ly*inv, uz = lz*inv;

    int pl = (lane + 31) & 31;
    float plx = __shfl_sync(FULL, lx, pl);
    float ply = __shfl_sync(FULL, ly, pl);
    float plz = __shfl_sync(FULL, lz, pl);
    float pnlx = __shfl_sync(FULL, nlx, pl);
    float pnly = __shfl_sync(FULL, nly, pl);
    float pnlz = __shfl_sync(FULL, nlz, pl);
    float pux = __shfl_sync(FULL, ux, pl);
    float puy = __shfl_sync(FULL, uy, pl);
    float puz = __shfl_sync(FULL, uz, pl);

    float ivx = lx - plx, ivy = ly - ply, ivz = lz - plz;
    float isq = ivx*ivx + ivy*ivy + ivz*ivz;
    float idn = (isq > 0.f) ? sqrtf(isq) : 0.f;
    float ii  = (idn > 0.f) ? (1.f / idn) : 0.f;
    float iux = ivx*ii, iuy = ivy*ii, iuz = ivz*ii;

    float a1 = ux*ax + uy*ay + uz*az;
    float a2 = ux*nlx + uy*nly + uz*nlz;
    float a3 = acosf(clamp_ac(nlx*ax + nly*ay + nlz*az));
    float a4 = iux*nlx + iuy*nly + iuz*nlz;
    float a5 = iux*pnlx + iuy*pnly + iuz*pnlz;
    float a6 = acosf(clamp_ac(nlx*pnlx + nly*pnly + nlz*pnlz));
    float d2 = acosf(clamp_ac(ux*pux + uy*puy + uz*puz));

    size_t p = (size_t)(b*Sc + s)*Kc + lane;
    g_X0[0*(size_t)PP + p] = d1;
    g_X0[1*(size_t)PP + p] = d2;
    g_X0[2*(size_t)PP + p] = a1;
    g_X0[3*(size_t)PP + p] = a2;
    g_X0[4*(size_t)PP + p] = a3;
    g_X0[5*(size_t)PP + p] = a4;
    g_X0[6*(size_t)PP + p] = a5;
    g_X0[7*(size_t)PP + p] = a6;
}

// ---------------------------------------------------------------------------
// FFMA conv for layer 0 (8->32) only. Unchanged (passing).
// ---------------------------------------------------------------------------
template<int CIN, int COUT, int TILE_O, int MODE, int LAYER>
__global__ void __launch_bounds__(256) k_conv(const float* __restrict__ W,
                                              const float* __restrict__ bias)
{
    constexpr int OW = TILE_O / 16;
    constexpr int PL = (LAYER > 0) ? (LAYER - 1) : 0;

    const float* Xin  = (LAYER == 0) ? g_X0 : g_Y1;
    float*       Yout = (LAYER == 0) ? g_Y1 : g_Y2;

    __shared__ __align__(16) float sW[8][TILE_O];
    __shared__ __align__(16) float sX[8][128];
    __shared__ float sSc[CIN];
    __shared__ float sSh[CIN];

    int tid = threadIdx.x;
    int o0  = blockIdx.y * TILE_O;
    int p0  = blockIdx.x * 128;

    if (MODE >= 1) {
        if (tid < CIN) { sSc[tid] = g_scale[PL][tid]; sSh[tid] = g_shift[PL][tid]; }
    }
    __syncthreads();

    int tx = tid & 15, ty = tid >> 4;
    int kcl = tid >> 5;
    int pp4 = (tid & 31) * 4;

    float acc[OW][8];
    #pragma unroll
    for (int i = 0; i < OW; ++i)
        #pragma unroll
        for (int j = 0; j < 8; ++j) acc[i][j] = 0.f;

    #pragma unroll 1
    for (int cc = 0; cc < CIN/8; ++cc) {
        int c0 = cc * 8;
        for (int idx = tid; idx < TILE_O*8; idx += 256) {
            int o = idx & (TILE_O - 1), c = idx / TILE_O;
            sW[c][o] = W[(o0 + o)*CIN + c0 + c];
        }
        {
            int c = c0 + kcl;
            float4 v;
            if (MODE == 0) {
                v = *(const float4*)&Xin[(size_t)c*PP + p0 + pp4];
            } else {
                float4 r = *(const float4*)&Xin[(size_t)c*PP + p0 + pp4];
                float scv = sSc[c], shv = sSh[c];
                v.x = fmaxf(fmaf(r.x, scv, shv), 0.f);
                v.y = fmaxf(fmaf(r.y, scv, shv), 0.f);
                v.z = fmaxf(fmaf(r.z, scv, shv), 0.f);
                v.w = fmaxf(fmaf(r.w, scv, shv), 0.f);
            }
            *(float4*)&sX[kcl][pp4] = v;
        }
        __syncthreads();

        #pragma unroll
        for (int kc = 0; kc < 8; ++kc) {
            float4 xa = ((const float4*)sX[kc])[tx*2];
            float4 xb = ((const float4*)sX[kc])[tx*2 + 1];
            float xr[8] = {xa.x, xa.y, xa.z, xa.w, xb.x, xb.y, xb.z, xb.w};
            float wr[OW];
            if constexpr (OW == 4) {
                float4 wa = ((const float4*)sW[kc])[ty];
                wr[0]=wa.x; wr[1]=wa.y; wr[2]=wa.z; wr[3]=wa.w;
            } else {
                #pragma unroll
                for (int i = 0; i < OW; ++i) wr[i] = sW[kc][ty*OW + i];
            }
            #pragma unroll
            for (int i = 0; i < OW; ++i)
                #pragma unroll
                for (int j = 0; j < 8; ++j)
                    acc[i][j] = fmaf(wr[i], xr[j], acc[i][j]);
        }
        __syncthreads();
    }

    #pragma unroll
    for (int i = 0; i < OW; ++i) {
        int o = o0 + ty*OW + i;
        float bo = bias[o];
        float y[8];
        #pragma unroll
        for (int j = 0; j < 8; ++j) y[j] = acc[i][j] + bo;

        *(float4*)&Yout[(size_t)o*PP + p0 + tx*8]     = make_float4(y[0], y[1], y[2], y[3]);
        *(float4*)&Yout[(size_t)o*PP + p0 + tx*8 + 4] = make_float4(y[4], y[5], y[6], y[7]);

        float s1 = 0.f, s2 = 0.f;
        #pragma unroll
        for (int j = 0; j < 8; ++j) { s1 += y[j]; s2 += y[j]*y[j]; }
        #pragma unroll
        for (int off = 1; off <= 8; off <<= 1) {
            s1 += __shfl_xor_sync(0xffffffffu, s1, off);
            s2 += __shfl_xor_sync(0xffffffffu, s2, off);
        }
        if (tx == 0) {
            atomicAdd(&g_sum[LAYER][o], (double)s1);
            atomicAdd(&g_sq [LAYER][o], (double)s2);
        }
    }
}

// ===========================================================================
// h_fe2: fp16 warp-MMA conv2 (32->64), N-tile 128. Layer index 1.
// smem: X@0 (32 rows x 256B = 8K) W@8192 (64 rows x 128B = 8K) misc@16384.
// 512 thr, warps 2(m)x8(n), warp tile 32m x 16n. Output Y2 fp32 + stats[1].
// ===========================================================================
#define FE2_SMEM (16384 + 512)
__global__ void __launch_bounds__(512) h_fe2(const float* __restrict__ W,
                                             const float* __restrict__ bias)
{
    extern __shared__ char smem[];
    const uint32_t XH = 0, WH = 8192, MISC = 16384;
    float* sSc = (float*)(smem + MISC);
    float* sSh = (float*)(smem + MISC + 128);
    uint32_t sb = smem_u32(smem);

    int tid = threadIdx.x, lane = tid & 31, wid = tid >> 5;
    int wm = wid & 1, wn = wid >> 1;      // rows wm*32, cols wn*16

    if (tid < 32) { sSc[tid] = g_scale[0][tid]; sSh[tid] = g_shift[0][tid]; }

    // W (64x32) -> smem fp16, rows padded to 128B
    {
        int o = tid >> 3, c0 = (tid & 7) * 4;
        const float* wr = W + o*32 + c0;
        uint32_t rowb = (uint32_t)o * 128;
        #pragma unroll
        for (int j = 0; j < 2; ++j) {
            int c = c0 + 2*j;
            uint32_t h = packh2(wr[2*j], wr[2*j+1]);
            uint32_t byt = rowb + ((((c >> 3) ^ (o & 7)) & 7) << 4) + (c & 7)*2;
            *(uint32_t*)(smem + WH + byt) = h;
        }
    }

    int fc  = tid >> 4;              // 0..31 channel
    int fn0 = (tid & 15) * 8;        // position offset, step 8

    int r0 = wm*32 + (lane >> 2);
    float bs[4] = { bias[r0], bias[r0 + 8], bias[r0 + 16], bias[r0 + 24] };
    double d1a[4] = {0,0,0,0}, d2a[4] = {0,0,0,0};
    __syncthreads();

    for (int tile = blockIdx.x; tile < PP/128; tile += gridDim.x) {
        int p0 = tile * 128;
        __syncthreads();

        // ---- fill X = bn_relu(Y1) fp16, 256B rows ----
        {
            const float4* src = (const float4*)&g_Y1[(size_t)fc*PP + p0 + fn0];
            float scv = sSc[fc], shv = sSh[fc];
            uint32_t rowb = (uint32_t)fc * 256;
            uint32_t gran = (uint32_t)(((fn0 >> 3) ^ (fc & 7)) & 15) << 4;
            #pragma unroll
            for (int j = 0; j < 2; ++j) {
                float4 r = src[j];
                float v0 = fmaxf(fmaf(r.x, scv, shv), 0.f);
                float v1 = fmaxf(fmaf(r.y, scv, shv), 0.f);
                float v2 = fmaxf(fmaf(r.z, scv, shv), 0.f);
                float v3 = fmaxf(fmaf(r.w, scv, shv), 0.f);
                int n = fn0 + 4*j;
                *(uint32_t*)(smem + XH + rowb + gran + (n & 7)*2)       = packh2(v0, v1);
                *(uint32_t*)(smem + XH + rowb + gran + ((n + 2) & 7)*2) = packh2(v2, v3);
            }
        }
        __syncthreads();

        // ---- MMA: 2 k-steps ----
        float acc[2][2][4];
        #pragma unroll
        for (int i = 0; i < 2; ++i)
            #pragma unroll
            for (int j = 0; j < 2; ++j)
                #pragma unroll
                for (int q = 0; q < 4; ++q) acc[i][j][q] = 0.f;

        #pragma unroll
        for (int s = 0; s < 2; ++s) {
            uint32_t A[8], B[4];
            #pragma unroll
            for (int mf = 0; mf < 2; ++mf) {
                int rr = wm*32 + mf*16 + (lane & 15);
                uint32_t g = (uint32_t)(2*s + (lane >> 4));
                uint32_t byt = (uint32_t)rr*128 + (((g ^ (rr & 7)) & 7) << 4);
                ldsm4(A + mf*4, sb + WH + byt);
            }
            {
                int ti = lane >> 3;
                int k = s*16 + (ti & 1)*8 + (lane & 7);
                int ng = (wn*16 >> 3) + (ti >> 1);
                uint32_t byt = (uint32_t)k*256 + (((ng ^ (k & 7)) & 15) << 4);
                ldsm4t(B, sb + XH + byt);
            }
            #pragma unroll
            for (int mf = 0; mf < 2; ++mf)
                #pragma unroll
                for (int nf = 0; nf < 2; ++nf)
                    mma_fp16(acc[mf][nf], A + mf*4, B + nf*2);
        }

        // ---- epilogue: bias, store Y2 fp32, stats[1] ----
        #pragma unroll
        for (int mf = 0; mf < 2; ++mf) {
            int r = wm*32 + mf*16 + (lane >> 2);
            float b0 = bs[mf*2], b1 = bs[mf*2 + 1];
            float s10 = 0.f, s20 = 0.f, s11 = 0.f, s21 = 0.f;
            #pragma unroll
            for (int nf = 0; nf < 2; ++nf) {
                int col = p0 + wn*16 + nf*8 + 2*(lane & 3);
                float y0 = acc[mf][nf][0] + b0, y1 = acc[mf][nf][1] + b0;
                float y2 = acc[mf][nf][2] + b1, y3 = acc[mf][nf][3] + b1;
                *(float2*)&g_Y2[(size_t)r*PP + col]       = make_float2(y0, y1);
                *(float2*)&g_Y2[(size_t)(r + 8)*PP + col] = make_float2(y2, y3);
                s10 += y0 + y1; s20 += y0*y0 + y1*y1;
                s11 += y2 + y3; s21 += y2*y2 + y3*y3;
            }
            #pragma unroll
            for (int off = 1; off <= 2; off <<= 1) {
                s10 += __shfl_xor_sync(0xffffffffu, s10, off);
                s20 += __shfl_xor_sync(0xffffffffu, s20, off);
                s11 += __shfl_xor_sync(0xffffffffu, s11, off);
                s21 += __shfl_xor_sync(0xffffffffu, s21, off);
            }
            if ((lane & 3) == 0) {
                d1a[mf*2]   += (double)s10; d2a[mf*2]   += (double)s20;
                d1a[mf*2+1] += (double)s11; d2a[mf*2+1] += (double)s21;
            }
        }
    }

    if ((lane & 3) == 0) {
        #pragma unroll
        for (int q = 0; q < 4; ++q) {
            int r = wm*32 + (q >> 1)*16 + (q & 1)*8 + (lane >> 2);
            atomicAdd(&g_sum[1][r], d1a[q]);
            atomicAdd(&g_sq [1][r], d2a[q]);
        }
    }
}

// ===========================================================================
// h_fl1: fp16 warp-MMA GEMM, layer 2 (128->128), N-tile 128.
// smem: X@0 (32K) W@32768 (32K) misc@65536. warps 4(m)x4(n).
// Y3 stored as fp16 (packed pairs).
// ===========================================================================
#define FL1_SMEM (65536 + 1024)
__global__ void __launch_bounds__(512) h_fl1(const float* __restrict__ W,
                                             const float* __restrict__ bias,
                                             const float* __restrict__ fmaps)
{
    extern __shared__ char smem[];
    const uint32_t XH = 0, WH = 32768, MISC = 65536;
    float* sSc = (float*)(smem + MISC);
    float* sSh = (float*)(smem + MISC + 256);
    uint32_t sb = smem_u32(smem);

    int tid = threadIdx.x, lane = tid & 31, wid = tid >> 5;
    int wm = wid & 3, wn = wid >> 2;

    if (tid < 64) { sSc[tid] = g_scale[1][tid]; sSh[tid] = g_shift[1][tid]; }

    // W -> smem fp16, swizzled rows of 256B
    {
        int o = tid >> 2, c0 = (tid & 3) * 32;
        const float* wr = W + o*128 + c0;
        uint32_t rowb = (uint32_t)o * 256;
        #pragma unroll
        for (int j = 0; j < 16; ++j) {
            int c = c0 + 2*j;
            uint32_t h = packh2(wr[2*j], wr[2*j+1]);
            uint32_t byt = rowb + ((((c >> 3) ^ (o & 7)) & 15) << 4) + (c & 7)*2;
            *(uint32_t*)(smem + WH + byt) = h;
        }
    }

    int fc  = tid >> 2;              // 0..127 channel
    int fn0 = (tid & 3) * 32;        // 0/32/64/96 position offset

    int r0 = wm*32 + (lane >> 2);
    float bs[4] = { bias[r0], bias[r0 + 8], bias[r0 + 16], bias[r0 + 24] };
    double d1a[4] = {0,0,0,0}, d2a[4] = {0,0,0,0};
    __syncthreads();

    for (int tile = blockIdx.x; tile < PP/128; tile += gridDim.x) {
        int p0 = tile * 128, bb = p0 >> 16;
        __syncthreads();   // prev iter's ldsm reads done before overwriting X

        // ---- fill X: bn_relu(Y2) for c<64, fmaps gather for c>=64 ----
        {
            float v[32];
            if (fc < 64) {
                const float4* src = (const float4*)&g_Y2[(size_t)fc*PP + p0 + fn0];
                float scv = sSc[fc], shv = sSh[fc];
                #pragma unroll
                for (int j = 0; j < 8; ++j) {
                    float4 r = src[j];
                    v[4*j+0] = fmaxf(fmaf(r.x, scv, shv), 0.f);
                    v[4*j+1] = fmaxf(fmaf(r.y, scv, shv), 0.f);
                    v[4*j+2] = fmaxf(fmaf(r.z, scv, shv), 0.f);
                    v[4*j+3] = fmaxf(fmaf(r.w, scv, shv), 0.f);
                }
            } else {
                const float* fp = fmaps + ((size_t)bb*Dc + (fc - 64))*Nn;
                const int4* gi = (const int4*)&g_gidx[(p0 & 65535) + fn0];
                #pragma unroll
                for (int j = 0; j < 8; ++j) {
                    int4 ix = gi[j];
                    v[4*j+0] = fp[ix.x];
                    v[4*j+1] = fp[ix.y];
                    v[4*j+2] = fp[ix.z];
                    v[4*j+3] = fp[ix.w];
                }
            }
            uint32_t rowb = (uint32_t)fc * 256;
            #pragma unroll
            for (int j = 0; j < 16; ++j) {
                int n = fn0 + 2*j;
                uint32_t h = packh2(v[2*j], v[2*j+1]);
                uint32_t byt = rowb + ((((n >> 3) ^ (fc & 7)) & 15) << 4) + (n & 7)*2;
                *(uint32_t*)(smem + XH + byt) = h;
            }
        }
        __syncthreads();

        // ---- MMA ----
        float acc[2][4][4];
        #pragma unroll
        for (int i = 0; i < 2; ++i)
            #pragma unroll
            for (int j = 0; j < 4; ++j)
                #pragma unroll
                for (int q = 0; q < 4; ++q) acc[i][j][q] = 0.f;

        #pragma unroll
        for (int s = 0; s < 8; ++s) {
            uint32_t A[8], B[8];
            #pragma unroll
            for (int mf = 0; mf < 2; ++mf) {
                int rr = wm*32 + mf*16 + (lane & 15);
                uint32_t g = (uint32_t)(2*s + (lane >> 4));
                uint32_t byt = (uint32_t)rr*256 + (((g ^ (rr & 7)) & 15) << 4);
                ldsm4(A + mf*4, sb + WH + byt);
            }
            #pragma unroll
            for (int half = 0; half < 2; ++half) {
                int ti = lane >> 3;
                int k = s*16 + (ti & 1)*8 + (lane & 7);
                int ng = ((wn*32 + half*16) >> 3) + (ti >> 1);
                uint32_t byt = (uint32_t)k*256 + (((ng ^ (k & 7)) & 15) << 4);
                ldsm4t(B + half*4, sb + XH + byt);
            }
            #pragma unroll
            for (int mf = 0; mf < 2; ++mf)
                #pragma unroll
                for (int nf = 0; nf < 4; ++nf)
                    mma_fp16(acc[mf][nf], A + mf*4, B + nf*2);
        }

        // ---- epilogue: bias, store Y3 as fp16 pairs, stats ----
        uint32_t* y3h = (uint32_t*)g_Y3;
        #pragma unroll
        for (int mf = 0; mf < 2; ++mf) {
            int r = wm*32 + mf*16 + (lane >> 2);
            float b0 = bs[mf*2], b1 = bs[mf*2 + 1];
            float s10 = 0.f, s20 = 0.f, s11 = 0.f, s21 = 0.f;
            #pragma unroll
            for (int nf = 0; nf < 4; ++nf) {
                int col = p0 + wn*32 + nf*8 + 2*(lane & 3);
                float y0 = acc[mf][nf][0] + b0, y1 = acc[mf][nf][1] + b0;
                float y2 = acc[mf][nf][2] + b1, y3 = acc[mf][nf][3] + b1;
                y3h[((size_t)r*PP + col) >> 1]       = packh2(y0, y1);
                y3h[((size_t)(r + 8)*PP + col) >> 1] = packh2(y2, y3);
                s10 += y0 + y1; s20 += y0*y0 + y1*y1;
                s11 += y2 + y3; s21 += y2*y2 + y3*y3;
            }
            #pragma unroll
            for (int off = 1; off <= 2; off <<= 1) {
                s10 += __shfl_xor_sync(0xffffffffu, s10, off);
                s20 += __shfl_xor_sync(0xffffffffu, s20, off);
                s11 += __shfl_xor_sync(0xffffffffu, s11, off);
                s21 += __shfl_xor_sync(0xffffffffu, s21, off);
            }
            if ((lane & 3) == 0) {
                d1a[mf*2]   += (double)s10; d2a[mf*2]   += (double)s20;
                d1a[mf*2+1] += (double)s11; d2a[mf*2+1] += (double)s21;
            }
        }
    }

    if ((lane & 3) == 0) {
        #pragma unroll
        for (int q = 0; q < 4; ++q) {
            int r = wm*32 + (q >> 1)*16 + (q & 1)*8 + (lane >> 2);
            atomicAdd(&g_sum[2][r], d1a[q]);
            atomicAdd(&g_sq [2][r], d2a[q]);
        }
    }
}

// ===========================================================================
// h_fl2: fp16 warp-MMA GEMM, layer 3 (128->256), N-tile 64.
// Reads Y3 as fp16, BN+relu applied in fp32 during fill.
// smem: X@0 (16K) W@16384 (64K) misc@81920. warps 8(m)x2(n).
// Epilogue: per-lane k-group max/min (no Y4).
// ===========================================================================
#define FL2_SMEM (81920 + 1024)
__global__ void __launch_bounds__(512) h_fl2(const float* __restrict__ W,
                                             const float* __restrict__ bias)
{
    extern __shared__ char smem[];
    const uint32_t XH = 0, WH = 16384, MISC = 81920;
    float* sSc = (float*)(smem + MISC);
    float* sSh = (float*)(smem + MISC + 512);
    uint32_t sb = smem_u32(smem);

    int tid = threadIdx.x, lane = tid & 31, wid = tid >> 5;
    int wm = wid >> 1, wn = wid & 1;

    if (tid < 128) { sSc[tid] = g_scale[2][tid]; sSh[tid] = g_shift[2][tid]; }

    // W2 (256x128) -> smem fp16, 256B rows
    {
        int o = tid >> 1, c0 = (tid & 1) * 64;
        const float* wr = W + o*128 + c0;
        uint32_t rowb = (uint32_t)o * 256;
        #pragma unroll
        for (int j = 0; j < 32; ++j) {
            int c = c0 + 2*j;
            uint32_t h = packh2(wr[2*j], wr[2*j+1]);
            uint32_t byt = rowb + ((((c >> 3) ^ (o & 7)) & 15) << 4) + (c & 7)*2;
            *(uint32_t*)(smem + WH + byt) = h;
        }
    }

    int fc  = tid >> 2;              // 0..127 channel
    int fn0 = (tid & 3) * 16;        // 0/16/32/48

    int r0 = wm*32 + (lane >> 2);
    float bs[4] = { bias[r0], bias[r0 + 8], bias[r0 + 16], bias[r0 + 24] };
    double d1a[4] = {0,0,0,0}, d2a[4] = {0,0,0,0};
    __syncthreads();

    for (int tile = blockIdx.x; tile < PP/64; tile += gridDim.x) {
        int p0 = tile * 64;
        __syncthreads();

        // ---- fill X = bn_relu(fp16 Y3) -> fp16, 128B rows ----
        {
            const int4* src = (const int4*)((const __half*)g_Y3 + (size_t)fc*PP + p0 + fn0);
            int4 raw0 = src[0];     // 8 halves (positions fn0..fn0+7)
            int4 raw1 = src[1];     // 8 halves (positions fn0+8..fn0+15)
            uint32_t rw[8] = { (uint32_t)raw0.x, (uint32_t)raw0.y, (uint32_t)raw0.z, (uint32_t)raw0.w,
                               (uint32_t)raw1.x, (uint32_t)raw1.y, (uint32_t)raw1.z, (uint32_t)raw1.w };
            float scv = sSc[fc], shv = sSh[fc];
            uint32_t rowb = (uint32_t)fc * 128;
            #pragma unroll
            for (int j = 0; j < 8; ++j) {
                float a, b;
                unpackh2(rw[j], a, b);
                float v0 = fmaxf(fmaf(a, scv, shv), 0.f);
                float v1 = fmaxf(fmaf(b, scv, shv), 0.f);
                int n = fn0 + 2*j;
                uint32_t byt = rowb + ((((n >> 3) ^ (fc & 7)) & 7) << 4) + (n & 7)*2;
                *(uint32_t*)(smem + XH + byt) = packh2(v0, v1);
            }
        }
        __syncthreads();

        // ---- MMA ----
        float acc[2][4][4];
        #pragma unroll
        for (int i = 0; i < 2; ++i)
            #pragma unroll
            for (int j = 0; j < 4; ++j)
                #pragma unroll
                for (int q = 0; q < 4; ++q) acc[i][j][q] = 0.f;

        #pragma unroll
        for (int s = 0; s < 8; ++s) {
            uint32_t A[8], B[8];
            #pragma unroll
            for (int mf = 0; mf < 2; ++mf) {
                int rr = wm*32 + mf*16 + (lane & 15);
                uint32_t g = (uint32_t)(2*s + (lane >> 4));
                uint32_t byt = (uint32_t)rr*256 + (((g ^ (rr & 7)) & 15) << 4);
                ldsm4(A + mf*4, sb + WH + byt);
            }
            #pragma unroll
            for (int half = 0; half < 2; ++half) {
                int ti = lane >> 3;
                int k = s*16 + (ti & 1)*8 + (lane & 7);
                int ng = ((wn*32 + half*16) >> 3) + (ti >> 1);
                uint32_t byt = (uint32_t)k*128 + (((ng ^ (k & 7)) & 7) << 4);
                ldsm4t(B + half*4, sb + XH + byt);
            }
            #pragma unroll
            for (int mf = 0; mf < 2; ++mf)
                #pragma unroll
                for (int nf = 0; nf < 4; ++nf)
                    mma_fp16(acc[mf][nf], A + mf*4, B + nf*2);
        }

        // ---- epilogue: k-group max/min + stats ----
        int grp = tile*2 + wn;
        #pragma unroll
        for (int mf = 0; mf < 2; ++mf) {
            int r = wm*32 + mf*16 + (lane >> 2);
            float b0 = bs[mf*2], b1 = bs[mf*2 + 1];
            float mx0 = -1e30f, mn0 = 1e30f, mx1 = -1e30f, mn1 = 1e30f;
            float s10 = 0.f, s20 = 0.f, s11 = 0.f, s21 = 0.f;
            #pragma unroll
            for (int nf = 0; nf < 4; ++nf) {
                float y0 = acc[mf][nf][0] + b0, y1 = acc[mf][nf][1] + b0;
                float y2 = acc[mf][nf][2] + b1, y3 = acc[mf][nf][3] + b1;
                mx0 = fmaxf(mx0, fmaxf(y0, y1)); mn0 = fminf(mn0, fminf(y0, y1));
                mx1 = fmaxf(mx1, fmaxf(y2, y3)); mn1 = fminf(mn1, fminf(y2, y3));
                s10 += y0 + y1; s20 += y0*y0 + y1*y1;
                s11 += y2 + y3; s21 += y2*y2 + y3*y3;
            }
            #pragma unroll
            for (int off = 1; off <= 2; off <<= 1) {
                mx0 = fmaxf(mx0, __shfl_xor_sync(0xffffffffu, mx0, off));
                mn0 = fminf(mn0, __shfl_xor_sync(0xffffffffu, mn0, off));
                mx1 = fmaxf(mx1, __shfl_xor_sync(0xffffffffu, mx1, off));
                mn1 = fminf(mn1, __shfl_xor_sync(0xffffffffu, mn1, off));
                s10 += __shfl_xor_sync(0xffffffffu, s10, off);
                s20 += __shfl_xor_sync(0xffffffffu, s20, off);
                s11 += __shfl_xor_sync(0xffffffffu, s11, off);
                s21 += __shfl_xor_sync(0xffffffffu, s21, off);
            }
            if ((lane & 3) == 0) {
                g_mx[(size_t)r*NG + grp]       = mx0;
                g_mn[(size_t)r*NG + grp]       = mn0;
                g_mx[(size_t)(r + 8)*NG + grp] = mx1;
                g_mn[(size_t)(r + 8)*NG + grp] = mn1;
                d1a[mf*2]   += (double)s10; d2a[mf*2]   += (double)s20;
                d1a[mf*2+1] += (double)s11; d2a[mf*2+1] += (double)s21;
            }
        }
    }

    if ((lane & 3) == 0) {
        #pragma unroll
        for (int q = 0; q < 4; ++q) {
            int r = wm*32 + (q >> 1)*16 + (q & 1)*8 + (lane >> 2);
            atomicAdd(&g_sum[3][r], d1a[q]);
            atomicAdd(&g_sq [3][r], d2a[q]);
        }
    }
}

// ---------------------------------------------------------------------------
__global__ void k_finalize(int layer, const float* __restrict__ gamma,
                           const float* __restrict__ beta, int cout)
{
    int c = threadIdx.x;
    if (c < cout) {
        double mean = g_sum[layer][c] / (double)PP;
        double var  = g_sq [layer][c] / (double)PP - mean*mean;
        double invs = rsqrt(var + 1e-5);
        double sc   = (double)gamma[c] * invs;
        g_scale[layer][c] = (float)sc;
        g_shift[layer][c] = (float)((double)beta[c] - mean * sc);
    }
}

// ---------------------------------------------------------------------------
__global__ void __launch_bounds__(256) k_out(float* __restrict__ out)
{
    int t = blockIdx.x * blockDim.x + threadIdx.x;
    if (t >= Bc*256*Sc) return;
    int s = t & (Sc - 1);
    int o = (t >> 11) & 255;
    int b = t >> 19;
    float sc = g_scale[3][o], sh = g_shift[3][o];
    int grp = b*Sc + s;
    float v = (sc > 0.f) ? g_mx[(size_t)o*NG + grp] : g_mn[(size_t)o*NG + grp];
    out[2*Bc*Sc*3 + t] = fmaxf(fmaf(v, sc, sh), 0.f);
}

// ---------------------------------------------------------------------------
extern "C" void kernel_launch(void* const* d_in, const int* in_sizes, int n_in,
                              void* d_out, int out_size)
{
    const float* contour = (const float*)d_in[0];
    const float* loa     = (const float*)d_in[1];
    const float* fmaps   = (const float*)d_in[2];
    const float* fe_w1   = (const float*)d_in[3];
    const float* fe_b1   = (const float*)d_in[4];
    const float* fe_g1   = (const float*)d_in[5];
    const float* fe_be1  = (const float*)d_in[6];
    const float* fe_w2   = (const float*)d_in[7];
    const float* fe_b2   = (const float*)d_in[8];
    const float* fe_g2   = (const float*)d_in[9];
    const float* fe_be2  = (const float*)d_in[10];
    const float* fl_w1   = (const float*)d_in[11];
    const float* fl_b1   = (const float*)d_in[12];
    const float* fl_g1   = (const float*)d_in[13];
    const float* fl_be1  = (const float*)d_in[14];
    const float* fl_w2   = (const float*)d_in[15];
    const float* fl_b2   = (const float*)d_in[16];
    const float* fl_g2   = (const float*)d_in[17];
    const float* fl_be2  = (const float*)d_in[18];
    float* out = (float*)d_out;

    cudaFuncSetAttribute(h_fe2, cudaFuncAttributeMaxDynamicSharedMemorySize, FE2_SMEM);
    cudaFuncSetAttribute(h_fl1, cudaFuncAttributeMaxDynamicSharedMemorySize, FL1_SMEM);
    cudaFuncSetAttribute(h_fl2, cudaFuncAttributeMaxDynamicSharedMemorySize, FL2_SMEM);

    const int PBLK = PP / 128;   // 4096

    k_rif<<<Bc*Sc/8, 256>>>(contour, loa, out);

    k_conv<8, 32, 32, 0, 0><<<dim3(PBLK, 1), 256>>>(fe_w1, fe_b1);
    k_finalize<<<1, 256>>>(0, fe_g1, fe_be1, 32);

    h_fe2<<<296, 512, FE2_SMEM>>>(fe_w2, fe_b2);
    k_finalize<<<1, 256>>>(1, fe_g2, fe_be2, 64);

    h_fl1<<<296, 512, FL1_SMEM>>>(fl_w1, fl_b1, fmaps);
    k_finalize<<<1, 256>>>(2, fl_g1, fl_be1, 128);

    h_fl2<<<296, 512, FL2_SMEM>>>(fl_w2, fl_b2);
    k_finalize<<<1, 256>>>(3, fl_g2, fl_be2, 256);

    k_out<<<(Bc*256*Sc + 255)/256, 256>>>(out);
}

// round 15
// speedup vs baseline: 1.4925x; 1.0711x over previous
#include <cuda_runtime.h>
#include <cuda_bf16.h>
#include <cuda_fp16.h>
#include <math.h>
#include <stdint.h>

#define Bc 8
#define Nn 8192
#define Sc 2048
#define Kc 32
#define Dc 64
#define PP (Bc*Sc*Kc)   // 524288 positions
#define NG (PP/32)      // 16384 k-groups

// ---------------- scratch ---------------------------------------------------
__device__ float g_X0[8   * PP];
__device__ float g_Y1[16  * PP];   // __half[32*PP]
__device__ float g_Y2[32  * PP];   // __half[64*PP]
__device__ float g_Y3[64  * PP];   // __half[128*PP]
__device__ float g_mx[256 * NG];
__device__ float g_mn[256 * NG];
__device__ int   g_gidx[Sc*Kc];
__device__ double g_sum[4][256];
__device__ double g_sq [4][256];
__device__ float g_scale[4][256];
__device__ float g_shift[4][256];

__device__ __forceinline__ float clamp_ac(float x) {
    return fminf(fmaxf(x, -0.9999999f), 0.9999999f);
}

// =================== warp MMA helpers (baseline PTX) =======================
__device__ __forceinline__ uint32_t smem_u32(const void* p) {
    uint32_t a;
    asm("{ .reg .u64 t; cvta.to.shared.u64 t, %1; cvt.u32.u64 %0, t; }"
        : "=r"(a) : "l"(p));
    return a;
}
__device__ __forceinline__ void ldsm4(uint32_t* r, uint32_t a) {
    asm volatile("ldmatrix.sync.aligned.m8n8.x4.shared.b16 {%0,%1,%2,%3}, [%4];"
        : "=r"(r[0]), "=r"(r[1]), "=r"(r[2]), "=r"(r[3]) : "r"(a));
}
__device__ __forceinline__ void ldsm4t(uint32_t* r, uint32_t a) {
    asm volatile("ldmatrix.sync.aligned.m8n8.x4.trans.shared.b16 {%0,%1,%2,%3}, [%4];"
        : "=r"(r[0]), "=r"(r[1]), "=r"(r[2]), "=r"(r[3]) : "r"(a));
}
__device__ __forceinline__ void mma_fp16(float* d, const uint32_t* a, const uint32_t* b) {
    asm volatile("mma.sync.aligned.m16n8k16.row.col.f32.f16.f16.f32 "
        "{%0,%1,%2,%3}, {%4,%5,%6,%7}, {%8,%9}, {%0,%1,%2,%3};"
        : "+f"(d[0]), "+f"(d[1]), "+f"(d[2]), "+f"(d[3])
        : "r"(a[0]), "r"(a[1]), "r"(a[2]), "r"(a[3]), "r"(b[0]), "r"(b[1]));
}
__device__ __forceinline__ uint32_t packh2(float a, float b) {
    uint32_t r;
    asm("cvt.rn.f16x2.f32 %0, %1, %2;" : "=r"(r) : "f"(b), "f"(a));
    return r;
}
__device__ __forceinline__ void unpackh2(uint32_t h, float& a, float& b) {
    __half2 v = *(__half2*)&h;
    float2 f = __half22float2(v);
    a = f.x; b = f.y;
}

// ---------------------------------------------------------------------------
// k_rif: unchanged (passing since R5).
// ---------------------------------------------------------------------------
__global__ void __launch_bounds__(256) k_rif(const float* __restrict__ contour,
                                             const float* __restrict__ loa,
                                             float* __restrict__ out)
{
    const unsigned FULL = 0xffffffffu;
    int tid  = threadIdx.x;
    if (blockIdx.x == 0) {
        #pragma unroll
        for (int j = 0; j < 4; ++j) {
            ((double*)g_sum)[tid + j*256] = 0.0;
            ((double*)g_sq )[tid + j*256] = 0.0;
        }
    }
    int w    = blockIdx.x * 8 + (tid >> 5);
    int lane = tid & 31;
    int b = w >> 11;
    int s = w & (Sc - 1);

    int i0;
    if (s == Sc - 1) i0 = Nn - 1;
    else {
        float t = __fdiv_rn((float)s, 2047.0f);
        float v = __fmul_rn(8191.0f, t);
        i0 = (int)v;
    }
    int n = (i0 - (Kc/2) + lane) & (Nn - 1);
    if (b == 0) g_gidx[s*Kc + lane] = n;

    const float* cp = contour + ((size_t)b*Nn + i0)*3;
    float spx = cp[0], spy = cp[1], spz = cp[2];
    const float* ap = loa + ((size_t)b*Nn + i0)*3;
    float ax = ap[0], ay = ap[1], az = ap[2];

    if (lane < 3) {
        out[(b*Sc + s)*3 + lane]           = cp[lane];
        out[Bc*Sc*3 + (b*Sc + s)*3 + lane] = ap[lane];
    }

    const float* pp_ = contour + ((size_t)b*Nn + n)*3;
    float lx = pp_[0] - spx, ly = pp_[1] - spy, lz = pp_[2] - spz;
    const float* lp = loa + ((size_t)b*Nn + n)*3;
    float nlx = lp[0], nly = lp[1], nlz = lp[2];

    float sq = lx*lx + ly*ly + lz*lz;
    float d1 = (sq > 0.f) ? sqrtf(sq) : 0.f;
    float inv = (d1 > 0.f) ? (1.f / d1) : 0.f;
    float ux = lx*inv, uy = ly*inv, uz = lz*inv;

    int pl = (lane + 31) & 31;
    float plx = __shfl_sync(FULL, lx, pl);
    float ply = __shfl_sync(FULL, ly, pl);
    float plz = __shfl_sync(FULL, lz, pl);
    float pnlx = __shfl_sync(FULL, nlx, pl);
    float pnly = __shfl_sync(FULL, nly, pl);
    float pnlz = __shfl_sync(FULL, nlz, pl);
    float pux = __shfl_sync(FULL, ux, pl);
    float puy = __shfl_sync(FULL, uy, pl);
    float puz = __shfl_sync(FULL, uz, pl);

    float ivx = lx - plx, ivy = ly - ply, ivz = lz - plz;
    float isq = ivx*ivx + ivy*ivy + ivz*ivz;
    float idn = (isq > 0.f) ? sqrtf(isq) : 0.f;
    float ii  = (idn > 0.f) ? (1.f / idn) : 0.f;
    float iux = ivx*ii, iuy = ivy*ii, iuz = ivz*ii;

    float a1 = ux*ax + uy*ay + uz*az;
    float a2 = ux*nlx + uy*nly + uz*nlz;
    float a3 = acosf(clamp_ac(nlx*ax + nly*ay + nlz*az));
    float a4 = iux*nlx + iuy*nly + iuz*nlz;
    float a5 = iux*pnlx + iuy*pnly + iuz*pnlz;
    float a6 = acosf(clamp_ac(nlx*pnlx + nly*pnly + nlz*pnlz));
    float d2 = acosf(clamp_ac(ux*pux + uy*puy + uz*puz));

    size_t p = (size_t)(b*Sc + s)*Kc + lane;
    g_X0[0*(size_t)PP + p] = d1;
    g_X0[1*(size_t)PP + p] = d2;
    g_X0[2*(size_t)PP + p] = a1;
    g_X0[3*(size_t)PP + p] = a2;
    g_X0[4*(size_t)PP + p] = a3;
    g_X0[5*(size_t)PP + p] = a4;
    g_X0[6*(size_t)PP + p] = a5;
    g_X0[7*(size_t)PP + p] = a6;
}

// ---------------------------------------------------------------------------
// k_conv0: FFMA conv layer 0 (8->32), raw X0 in, Y1 out as fp16. Stats[0].
// ---------------------------------------------------------------------------
__global__ void __launch_bounds__(256) k_conv0(const float* __restrict__ W,
                                               const float* __restrict__ bias)
{
    __shared__ __align__(16) float sW[8][32];
    __shared__ __align__(16) float sX[8][128];

    int tid = threadIdx.x;
    int p0  = blockIdx.x * 128;

    int tx = tid & 15, ty = tid >> 4;
    int kcl = tid >> 5;
    int pp4 = (tid & 31) * 4;

    if (tid < 256) {
        int o = tid & 31, c = tid >> 5;
        sW[c][o] = W[o*8 + c];
    }
    *(float4*)&sX[kcl][pp4] = *(const float4*)&g_X0[(size_t)kcl*PP + p0 + pp4];
    __syncthreads();

    float acc[2][8];
    #pragma unroll
    for (int i = 0; i < 2; ++i)
        #pragma unroll
        for (int j = 0; j < 8; ++j) acc[i][j] = 0.f;

    #pragma unroll
    for (int kc = 0; kc < 8; ++kc) {
        float4 xa = ((const float4*)sX[kc])[tx*2];
        float4 xb = ((const float4*)sX[kc])[tx*2 + 1];
        float xr[8] = {xa.x, xa.y, xa.z, xa.w, xb.x, xb.y, xb.z, xb.w};
        float w0 = sW[kc][ty*2], w1 = sW[kc][ty*2 + 1];
        #pragma unroll
        for (int j = 0; j < 8; ++j) {
            acc[0][j] = fmaf(w0, xr[j], acc[0][j]);
            acc[1][j] = fmaf(w1, xr[j], acc[1][j]);
        }
    }

    uint32_t* y1h = (uint32_t*)g_Y1;
    #pragma unroll
    for (int i = 0; i < 2; ++i) {
        int o = ty*2 + i;
        float bo = bias[o];
        float y[8];
        #pragma unroll
        for (int j = 0; j < 8; ++j) y[j] = acc[i][j] + bo;

        size_t base = ((size_t)o*PP + p0 + tx*8) >> 1;
        y1h[base + 0] = packh2(y[0], y[1]);
        y1h[base + 1] = packh2(y[2], y[3]);
        y1h[base + 2] = packh2(y[4], y[5]);
        y1h[base + 3] = packh2(y[6], y[7]);

        float s1 = 0.f, s2 = 0.f;
        #pragma unroll
        for (int j = 0; j < 8; ++j) { s1 += y[j]; s2 += y[j]*y[j]; }
        #pragma unroll
        for (int off = 1; off <= 8; off <<= 1) {
            s1 += __shfl_xor_sync(0xffffffffu, s1, off);
            s2 += __shfl_xor_sync(0xffffffffu, s2, off);
        }
        if (tx == 0) {
            atomicAdd(&g_sum[0][o], (double)s1);
            atomicAdd(&g_sq [0][o], (double)s2);
        }
    }
}

// ===========================================================================
// h_fe2: fp16 warp-MMA conv2 (32->64), N-tile 256. Layer index 1.
// smem: X@0 (32 rows x 512B = 16K) W@16384 (64 x 128B = 8K) misc@24576.
// 512 thr, warps 2(m)x8(n), warp tile 32m x 32n. Y1 fp16 in, Y2 fp16 out.
// ===========================================================================
#define FE2_SMEM (24576 + 512)
__global__ void __launch_bounds__(512) h_fe2(const float* __restrict__ W,
                                             const float* __restrict__ bias)
{
    extern __shared__ char smem[];
    const uint32_t XH = 0, WH = 16384, MISC = 24576;
    float* sSc = (float*)(smem + MISC);
    float* sSh = (float*)(smem + MISC + 128);
    uint32_t sb = smem_u32(smem);

    int tid = threadIdx.x, lane = tid & 31, wid = tid >> 5;
    int wm = wid & 1, wn = wid >> 1;      // rows wm*32, cols wn*32

    if (tid < 32) { sSc[tid] = g_scale[0][tid]; sSh[tid] = g_shift[0][tid]; }

    // W (64x32) -> smem fp16, rows padded to 128B
    {
        int o = tid >> 3, c0 = (tid & 7) * 4;
        const float* wr = W + o*32 + c0;
        uint32_t rowb = (uint32_t)o * 128;
        #pragma unroll
        for (int j = 0; j < 2; ++j) {
            int c = c0 + 2*j;
            uint32_t h = packh2(wr[2*j], wr[2*j+1]);
            uint32_t byt = rowb + ((((c >> 3) ^ (o & 7)) & 7) << 4) + (c & 7)*2;
            *(uint32_t*)(smem + WH + byt) = h;
        }
    }

    int fc  = tid >> 4;              // 0..31 channel
    int fn0 = (tid & 15) * 16;       // position offset, step 16

    int r0 = wm*32 + (lane >> 2);
    float bs[4] = { bias[r0], bias[r0 + 8], bias[r0 + 16], bias[r0 + 24] };
    double d1a[4] = {0,0,0,0}, d2a[4] = {0,0,0,0};
    __syncthreads();

    for (int tile = blockIdx.x; tile < PP/256; tile += gridDim.x) {
        int p0 = tile * 256;
        __syncthreads();

        // ---- fill X = bn_relu(fp16 Y1) -> fp16, 512B rows ----
        {
            const int4* src = (const int4*)((const __half*)g_Y1 + (size_t)fc*PP + p0 + fn0);
            int4 raw0 = src[0], raw1 = src[1];
            uint32_t rw[8] = { (uint32_t)raw0.x, (uint32_t)raw0.y, (uint32_t)raw0.z, (uint32_t)raw0.w,
                               (uint32_t)raw1.x, (uint32_t)raw1.y, (uint32_t)raw1.z, (uint32_t)raw1.w };
            float scv = sSc[fc], shv = sSh[fc];
            uint32_t rowb = (uint32_t)fc * 512;
            #pragma unroll
            for (int j = 0; j < 8; ++j) {
                float a, b;
                unpackh2(rw[j], a, b);
                float v0 = fmaxf(fmaf(a, scv, shv), 0.f);
                float v1 = fmaxf(fmaf(b, scv, shv), 0.f);
                int n = fn0 + 2*j;
                uint32_t byt = rowb + ((((n >> 3) ^ (fc & 7)) & 31) << 4) + (n & 7)*2;
                *(uint32_t*)(smem + XH + byt) = packh2(v0, v1);
            }
        }
        __syncthreads();

        // ---- MMA: 2 k-steps ----
        float acc[2][4][4];
        #pragma unroll
        for (int i = 0; i < 2; ++i)
            #pragma unroll
            for (int j = 0; j < 4; ++j)
                #pragma unroll
                for (int q = 0; q < 4; ++q) acc[i][j][q] = 0.f;

        #pragma unroll
        for (int s = 0; s < 2; ++s) {
            uint32_t A[8], B[8];
            #pragma unroll
            for (int mf = 0; mf < 2; ++mf) {
                int rr = wm*32 + mf*16 + (lane & 15);
                uint32_t g = (uint32_t)(2*s + (lane >> 4));
                uint32_t byt = (uint32_t)rr*128 + (((g ^ (rr & 7)) & 7) << 4);
                ldsm4(A + mf*4, sb + WH + byt);
            }
            #pragma unroll
            for (int half = 0; half < 2; ++half) {
                int ti = lane >> 3;
                int k = s*16 + (ti & 1)*8 + (lane & 7);
                int ng = ((wn*32 + half*16) >> 3) + (ti >> 1);
                uint32_t byt = (uint32_t)k*512 + (((ng ^ (k & 7)) & 31) << 4);
                ldsm4t(B + half*4, sb + XH + byt);
            }
            #pragma unroll
            for (int mf = 0; mf < 2; ++mf)
                #pragma unroll
                for (int nf = 0; nf < 4; ++nf)
                    mma_fp16(acc[mf][nf], A + mf*4, B + nf*2);
        }

        // ---- epilogue: bias, store Y2 fp16, stats[1] ----
        uint32_t* y2h = (uint32_t*)g_Y2;
        #pragma unroll
        for (int mf = 0; mf < 2; ++mf) {
            int r = wm*32 + mf*16 + (lane >> 2);
            float b0 = bs[mf*2], b1 = bs[mf*2 + 1];
            float s10 = 0.f, s20 = 0.f, s11 = 0.f, s21 = 0.f;
            #pragma unroll
            for (int nf = 0; nf < 4; ++nf) {
                int col = p0 + wn*32 + nf*8 + 2*(lane & 3);
                float y0 = acc[mf][nf][0] + b0, y1 = acc[mf][nf][1] + b0;
                float y2 = acc[mf][nf][2] + b1, y3 = acc[mf][nf][3] + b1;
                y2h[((size_t)r*PP + col) >> 1]       = packh2(y0, y1);
                y2h[((size_t)(r + 8)*PP + col) >> 1] = packh2(y2, y3);
                s10 += y0 + y1; s20 += y0*y0 + y1*y1;
                s11 += y2 + y3; s21 += y2*y2 + y3*y3;
            }
            #pragma unroll
            for (int off = 1; off <= 2; off <<= 1) {
                s10 += __shfl_xor_sync(0xffffffffu, s10, off);
                s20 += __shfl_xor_sync(0xffffffffu, s20, off);
                s11 += __shfl_xor_sync(0xffffffffu, s11, off);
                s21 += __shfl_xor_sync(0xffffffffu, s21, off);
            }
            if ((lane & 3) == 0) {
                d1a[mf*2]   += (double)s10; d2a[mf*2]   += (double)s20;
                d1a[mf*2+1] += (double)s11; d2a[mf*2+1] += (double)s21;
            }
        }
    }

    if ((lane & 3) == 0) {
        #pragma unroll
        for (int q = 0; q < 4; ++q) {
            int r = wm*32 + (q >> 1)*16 + (q & 1)*8 + (lane >> 2);
            atomicAdd(&g_sum[1][r], d1a[q]);
            atomicAdd(&g_sq [1][r], d2a[q]);
        }
    }
}

// ===========================================================================
// h_fl1: fp16 warp-MMA GEMM, layer 2 (128->128), N-tile 128.
// Reads Y2 fp16 (c<64) + fmaps gather (c>=64); writes Y3 fp16.
// smem: X@0 (32K) W@32768 (32K) misc@65536. warps 4(m)x4(n).
// ===========================================================================
#define FL1_SMEM (65536 + 1024)
__global__ void __launch_bounds__(512) h_fl1(const float* __restrict__ W,
                                             const float* __restrict__ bias,
                                             const float* __restrict__ fmaps)
{
    extern __shared__ char smem[];
    const uint32_t XH = 0, WH = 32768, MISC = 65536;
    float* sSc = (float*)(smem + MISC);
    float* sSh = (float*)(smem + MISC + 256);
    uint32_t sb = smem_u32(smem);

    int tid = threadIdx.x, lane = tid & 31, wid = tid >> 5;
    int wm = wid & 3, wn = wid >> 2;

    if (tid < 64) { sSc[tid] = g_scale[1][tid]; sSh[tid] = g_shift[1][tid]; }

    // W -> smem fp16, swizzled rows of 256B
    {
        int o = tid >> 2, c0 = (tid & 3) * 32;
        const float* wr = W + o*128 + c0;
        uint32_t rowb = (uint32_t)o * 256;
        #pragma unroll
        for (int j = 0; j < 16; ++j) {
            int c = c0 + 2*j;
            uint32_t h = packh2(wr[2*j], wr[2*j+1]);
            uint32_t byt = rowb + ((((c >> 3) ^ (o & 7)) & 15) << 4) + (c & 7)*2;
            *(uint32_t*)(smem + WH + byt) = h;
        }
    }

    int fc  = tid >> 2;              // 0..127 channel
    int fn0 = (tid & 3) * 32;        // 0/32/64/96 position offset

    int r0 = wm*32 + (lane >> 2);
    float bs[4] = { bias[r0], bias[r0 + 8], bias[r0 + 16], bias[r0 + 24] };
    double d1a[4] = {0,0,0,0}, d2a[4] = {0,0,0,0};
    __syncthreads();

    for (int tile = blockIdx.x; tile < PP/128; tile += gridDim.x) {
        int p0 = tile * 128, bb = p0 >> 16;
        __syncthreads();

        // ---- fill X: bn_relu(fp16 Y2) for c<64, fmaps gather for c>=64 ----
        {
            float v[32];
            if (fc < 64) {
                const int4* src = (const int4*)((const __half*)g_Y2 + (size_t)fc*PP + p0 + fn0);
                float scv = sSc[fc], shv = sSh[fc];
                #pragma unroll
                for (int j4 = 0; j4 < 4; ++j4) {
                    int4 raw = src[j4];
                    uint32_t rw[4] = { (uint32_t)raw.x, (uint32_t)raw.y,
                                       (uint32_t)raw.z, (uint32_t)raw.w };
                    #pragma unroll
                    for (int q = 0; q < 4; ++q) {
                        float a, b;
                        unpackh2(rw[q], a, b);
                        v[j4*8 + 2*q + 0] = fmaxf(fmaf(a, scv, shv), 0.f);
                        v[j4*8 + 2*q + 1] = fmaxf(fmaf(b, scv, shv), 0.f);
                    }
                }
            } else {
                const float* fp = fmaps + ((size_t)bb*Dc + (fc - 64))*Nn;
                const int4* gi = (const int4*)&g_gidx[(p0 & 65535) + fn0];
                #pragma unroll
                for (int j = 0; j < 8; ++j) {
                    int4 ix = gi[j];
                    v[4*j+0] = fp[ix.x];
                    v[4*j+1] = fp[ix.y];
                    v[4*j+2] = fp[ix.z];
                    v[4*j+3] = fp[ix.w];
                }
            }
            uint32_t rowb = (uint32_t)fc * 256;
            #pragma unroll
            for (int j = 0; j < 16; ++j) {
                int n = fn0 + 2*j;
                uint32_t h = packh2(v[2*j], v[2*j+1]);
                uint32_t byt = rowb + ((((n >> 3) ^ (fc & 7)) & 15) << 4) + (n & 7)*2;
                *(uint32_t*)(smem + XH + byt) = h;
            }
        }
        __syncthreads();

        // ---- MMA ----
        float acc[2][4][4];
        #pragma unroll
        for (int i = 0; i < 2; ++i)
            #pragma unroll
            for (int j = 0; j < 4; ++j)
                #pragma unroll
                for (int q = 0; q < 4; ++q) acc[i][j][q] = 0.f;

        #pragma unroll
        for (int s = 0; s < 8; ++s) {
            uint32_t A[8], B[8];
            #pragma unroll
            for (int mf = 0; mf < 2; ++mf) {
                int rr = wm*32 + mf*16 + (lane & 15);
                uint32_t g = (uint32_t)(2*s + (lane >> 4));
                uint32_t byt = (uint32_t)rr*256 + (((g ^ (rr & 7)) & 15) << 4);
                ldsm4(A + mf*4, sb + WH + byt);
            }
            #pragma unroll
            for (int half = 0; half < 2; ++half) {
                int ti = lane >> 3;
                int k = s*16 + (ti & 1)*8 + (lane & 7);
                int ng = ((wn*32 + half*16) >> 3) + (ti >> 1);
                uint32_t byt = (uint32_t)k*256 + (((ng ^ (k & 7)) & 15) << 4);
                ldsm4t(B + half*4, sb + XH + byt);
            }
            #pragma unroll
            for (int mf = 0; mf < 2; ++mf)
                #pragma unroll
                for (int nf = 0; nf < 4; ++nf)
                    mma_fp16(acc[mf][nf], A + mf*4, B + nf*2);
        }

        // ---- epilogue: bias, store Y3 fp16, stats ----
        uint32_t* y3h = (uint32_t*)g_Y3;
        #pragma unroll
        for (int mf = 0; mf < 2; ++mf) {
            int r = wm*32 + mf*16 + (lane >> 2);
            float b0 = bs[mf*2], b1 = bs[mf*2 + 1];
            float s10 = 0.f, s20 = 0.f, s11 = 0.f, s21 = 0.f;
            #pragma unroll
            for (int nf = 0; nf < 4; ++nf) {
                int col = p0 + wn*32 + nf*8 + 2*(lane & 3);
                float y0 = acc[mf][nf][0] + b0, y1 = acc[mf][nf][1] + b0;
                float y2 = acc[mf][nf][2] + b1, y3 = acc[mf][nf][3] + b1;
                y3h[((size_t)r*PP + col) >> 1]       = packh2(y0, y1);
                y3h[((size_t)(r + 8)*PP + col) >> 1] = packh2(y2, y3);
                s10 += y0 + y1; s20 += y0*y0 + y1*y1;
                s11 += y2 + y3; s21 += y2*y2 + y3*y3;
            }
            #pragma unroll
            for (int off = 1; off <= 2; off <<= 1) {
                s10 += __shfl_xor_sync(0xffffffffu, s10, off);
                s20 += __shfl_xor_sync(0xffffffffu, s20, off);
                s11 += __shfl_xor_sync(0xffffffffu, s11, off);
                s21 += __shfl_xor_sync(0xffffffffu, s21, off);
            }
            if ((lane & 3) == 0) {
                d1a[mf*2]   += (double)s10; d2a[mf*2]   += (double)s20;
                d1a[mf*2+1] += (double)s11; d2a[mf*2+1] += (double)s21;
            }
        }
    }

    if ((lane & 3) == 0) {
        #pragma unroll
        for (int q = 0; q < 4; ++q) {
            int r = wm*32 + (q >> 1)*16 + (q & 1)*8 + (lane >> 2);
            atomicAdd(&g_sum[2][r], d1a[q]);
            atomicAdd(&g_sq [2][r], d2a[q]);
        }
    }
}

// ===========================================================================
// h_fl2: fp16 warp-MMA GEMM, layer 3 (128->256), N-tile 64.
// Reads Y3 fp16. smem: X@0 (16K) W@16384 (64K) misc@81920. warps 8(m)x2(n).
// Epilogue: per-lane k-group max/min (no Y4).
// ===========================================================================
#define FL2_SMEM (81920 + 1024)
__global__ void __launch_bounds__(512) h_fl2(const float* __restrict__ W,
                                             const float* __restrict__ bias)
{
    extern __shared__ char smem[];
    const uint32_t XH = 0, WH = 16384, MISC = 81920;
    float* sSc = (float*)(smem + MISC);
    float* sSh = (float*)(smem + MISC + 512);
    uint32_t sb = smem_u32(smem);

    int tid = threadIdx.x, lane = tid & 31, wid = tid >> 5;
    int wm = wid >> 1, wn = wid & 1;

    if (tid < 128) { sSc[tid] = g_scale[2][tid]; sSh[tid] = g_shift[2][tid]; }

    // W2 (256x128) -> smem fp16, 256B rows
    {
        int o = tid >> 1, c0 = (tid & 1) * 64;
        const float* wr = W + o*128 + c0;
        uint32_t rowb = (uint32_t)o * 256;
        #pragma unroll
        for (int j = 0; j < 32; ++j) {
            int c = c0 + 2*j;
            uint32_t h = packh2(wr[2*j], wr[2*j+1]);
            uint32_t byt = rowb + ((((c >> 3) ^ (o & 7)) & 15) << 4) + (c & 7)*2;
            *(uint32_t*)(smem + WH + byt) = h;
        }
    }

    int fc  = tid >> 2;              // 0..127 channel
    int fn0 = (tid & 3) * 16;        // 0/16/32/48

    int r0 = wm*32 + (lane >> 2);
    float bs[4] = { bias[r0], bias[r0 + 8], bias[r0 + 16], bias[r0 + 24] };
    double d1a[4] = {0,0,0,0}, d2a[4] = {0,0,0,0};
    __syncthreads();

    for (int tile = blockIdx.x; tile < PP/64; tile += gridDim.x) {
        int p0 = tile * 64;
        __syncthreads();

        // ---- fill X = bn_relu(fp16 Y3) -> fp16, 128B rows ----
        {
            const int4* src = (const int4*)((const __half*)g_Y3 + (size_t)fc*PP + p0 + fn0);
            int4 raw0 = src[0];
            int4 raw1 = src[1];
            uint32_t rw[8] = { (uint32_t)raw0.x, (uint32_t)raw0.y, (uint32_t)raw0.z, (uint32_t)raw0.w,
                               (uint32_t)raw1.x, (uint32_t)raw1.y, (uint32_t)raw1.z, (uint32_t)raw1.w };
            float scv = sSc[fc], shv = sSh[fc];
            uint32_t rowb = (uint32_t)fc * 128;
            #pragma unroll
            for (int j = 0; j < 8; ++j) {
                float a, b;
                unpackh2(rw[j], a, b);
                float v0 = fmaxf(fmaf(a, scv, shv), 0.f);
                float v1 = fmaxf(fmaf(b, scv, shv), 0.f);
                int n = fn0 + 2*j;
                uint32_t byt = rowb + ((((n >> 3) ^ (fc & 7)) & 7) << 4) + (n & 7)*2;
                *(uint32_t*)(smem + XH + byt) = packh2(v0, v1);
            }
        }
        __syncthreads();

        // ---- MMA ----
        float acc[2][4][4];
        #pragma unroll
        for (int i = 0; i < 2; ++i)
            #pragma unroll
            for (int j = 0; j < 4; ++j)
                #pragma unroll
                for (int q = 0; q < 4; ++q) acc[i][j][q] = 0.f;

        #pragma unroll
        for (int s = 0; s < 8; ++s) {
            uint32_t A[8], B[8];
            #pragma unroll
            for (int mf = 0; mf < 2; ++mf) {
                int rr = wm*32 + mf*16 + (lane & 15);
                uint32_t g = (uint32_t)(2*s + (lane >> 4));
                uint32_t byt = (uint32_t)rr*256 + (((g ^ (rr & 7)) & 15) << 4);
                ldsm4(A + mf*4, sb + WH + byt);
            }
            #pragma unroll
            for (int half = 0; half < 2; ++half) {
                int ti = lane >> 3;
                int k = s*16 + (ti & 1)*8 + (lane & 7);
                int ng = ((wn*32 + half*16) >> 3) + (ti >> 1);
                uint32_t byt = (uint32_t)k*128 + (((ng ^ (k & 7)) & 7) << 4);
                ldsm4t(B + half*4, sb + XH + byt);
            }
            #pragma unroll
            for (int mf = 0; mf < 2; ++mf)
                #pragma unroll
                for (int nf = 0; nf < 4; ++nf)
                    mma_fp16(acc[mf][nf], A + mf*4, B + nf*2);
        }

        // ---- epilogue: k-group max/min + stats ----
        int grp = tile*2 + wn;
        #pragma unroll
        for (int mf = 0; mf < 2; ++mf) {
            int r = wm*32 + mf*16 + (lane >> 2);
            float b0 = bs[mf*2], b1 = bs[mf*2 + 1];
            float mx0 = -1e30f, mn0 = 1e30f, mx1 = -1e30f, mn1 = 1e30f;
            float s10 = 0.f, s20 = 0.f, s11 = 0.f, s21 = 0.f;
            #pragma unroll
            for (int nf = 0; nf < 4; ++nf) {
                float y0 = acc[mf][nf][0] + b0, y1 = acc[mf][nf][1] + b0;
                float y2 = acc[mf][nf][2] + b1, y3 = acc[mf][nf][3] + b1;
                mx0 = fmaxf(mx0, fmaxf(y0, y1)); mn0 = fminf(mn0, fminf(y0, y1));
                mx1 = fmaxf(mx1, fmaxf(y2, y3)); mn1 = fminf(mn1, fminf(y2, y3));
                s10 += y0 + y1; s20 += y0*y0 + y1*y1;
                s11 += y2 + y3; s21 += y2*y2 + y3*y3;
            }
            #pragma unroll
            for (int off = 1; off <= 2; off <<= 1) {
                mx0 = fmaxf(mx0, __shfl_xor_sync(0xffffffffu, mx0, off));
                mn0 = fminf(mn0, __shfl_xor_sync(0xffffffffu, mn0, off));
                mx1 = fmaxf(mx1, __shfl_xor_sync(0xffffffffu, mx1, off));
                mn1 = fminf(mn1, __shfl_xor_sync(0xffffffffu, mn1, off));
                s10 += __shfl_xor_sync(0xffffffffu, s10, off);
                s20 += __shfl_xor_sync(0xffffffffu, s20, off);
                s11 += __shfl_xor_sync(0xffffffffu, s11, off);
                s21 += __shfl_xor_sync(0xffffffffu, s21, off);
            }
            if ((lane & 3) == 0) {
                g_mx[(size_t)r*NG + grp]       = mx0;
                g_mn[(size_t)r*NG + grp]       = mn0;
                g_mx[(size_t)(r + 8)*NG + grp] = mx1;
                g_mn[(size_t)(r + 8)*NG + grp] = mn1;
                d1a[mf*2]   += (double)s10; d2a[mf*2]   += (double)s20;
                d1a[mf*2+1] += (double)s11; d2a[mf*2+1] += (double)s21;
            }
        }
    }

    if ((lane & 3) == 0) {
        #pragma unroll
        for (int q = 0; q < 4; ++q) {
            int r = wm*32 + (q >> 1)*16 + (q & 1)*8 + (lane >> 2);
            atomicAdd(&g_sum[3][r], d1a[q]);
            atomicAdd(&g_sq [3][r], d2a[q]);
        }
    }
}

// ---------------------------------------------------------------------------
__global__ void k_finalize(int layer, const float* __restrict__ gamma,
                           const float* __restrict__ beta, int cout)
{
    int c = threadIdx.x;
    if (c < cout) {
        double mean = g_sum[layer][c] / (double)PP;
        double var  = g_sq [layer][c] / (double)PP - mean*mean;
        double invs = rsqrt(var + 1e-5);
        double sc   = (double)gamma[c] * invs;
        g_scale[layer][c] = (float)sc;
        g_shift[layer][c] = (float)((double)beta[c] - mean * sc);
    }
}

// ---------------------------------------------------------------------------
__global__ void __launch_bounds__(256) k_out(float* __restrict__ out)
{
    int t = blockIdx.x * blockDim.x + threadIdx.x;
    if (t >= Bc*256*Sc) return;
    int s = t & (Sc - 1);
    int o = (t >> 11) & 255;
    int b = t >> 19;
    float sc = g_scale[3][o], sh = g_shift[3][o];
    int grp = b*Sc + s;
    float v = (sc > 0.f) ? g_mx[(size_t)o*NG + grp] : g_mn[(size_t)o*NG + grp];
    out[2*Bc*Sc*3 + t] = fmaxf(fmaf(v, sc, sh), 0.f);
}

// ---------------------------------------------------------------------------
extern "C" void kernel_launch(void* const* d_in, const int* in_sizes, int n_in,
                              void* d_out, int out_size)
{
    const float* contour = (const float*)d_in[0];
    const float* loa     = (const float*)d_in[1];
    const float* fmaps   = (const float*)d_in[2];
    const float* fe_w1   = (const float*)d_in[3];
    const float* fe_b1   = (const float*)d_in[4];
    const float* fe_g1   = (const float*)d_in[5];
    const float* fe_be1  = (const float*)d_in[6];
    const float* fe_w2   = (const float*)d_in[7];
    const float* fe_b2   = (const float*)d_in[8];
    const float* fe_g2   = (const float*)d_in[9];
    const float* fe_be2  = (const float*)d_in[10];
    const float* fl_w1   = (const float*)d_in[11];
    const float* fl_b1   = (const float*)d_in[12];
    const float* fl_g1   = (const float*)d_in[13];
    const float* fl_be1  = (const float*)d_in[14];
    const float* fl_w2   = (const float*)d_in[15];
    const float* fl_b2   = (const float*)d_in[16];
    const float* fl_g2   = (const float*)d_in[17];
    const float* fl_be2  = (const float*)d_in[18];
    float* out = (float*)d_out;

    cudaFuncSetAttribute(h_fe2, cudaFuncAttributeMaxDynamicSharedMemorySize, FE2_SMEM);
    cudaFuncSetAttribute(h_fl1, cudaFuncAttributeMaxDynamicSharedMemorySize, FL1_SMEM);
    cudaFuncSetAttribute(h_fl2, cudaFuncAttributeMaxDynamicSharedMemorySize, FL2_SMEM);

    k_rif<<<Bc*Sc/8, 256>>>(contour, loa, out);

    k_conv0<<<PP/128, 256>>>(fe_w1, fe_b1);
    k_finalize<<<1, 256>>>(0, fe_g1, fe_be1, 32);

    h_fe2<<<296, 512, FE2_SMEM>>>(fe_w2, fe_b2);
    k_finalize<<<1, 256>>>(1, fe_g2, fe_be2, 64);

    h_fl1<<<296, 512, FL1_SMEM>>>(fl_w1, fl_b1, fmaps);
    k_finalize<<<1, 256>>>(2, fl_g1, fl_be1, 128);

    h_fl2<<<296, 512, FL2_SMEM>>>(fl_w2, fl_b2);
    k_finalize<<<1, 256>>>(3, fl_g2, fl_be2, 256);

    k_out<<<(Bc*256*Sc + 255)/256, 256>>>(out);
}